// round 3
// baseline (speedup 1.0000x reference)
#include <cuda_runtime.h>
#include <cuda_bf16.h>

// Problem constants
#define Bq   2
#define Sq   2048
#define Dq   1024
#define Hq   16
#define HDq  64
#define NTOK (Bq * Sq)          // 4096
#define QKVN (3 * Dq)           // 3072

// Scratch (device globals: allocation-free rule)
__device__ float g_qkv[NTOK * QKVN];   // [4096][3072] : Q|K|V
__device__ float g_attn[NTOK * Dq];    // [4096][1024] : attention output (B,S,D)

// ---------------------------------------------------------------------------
// SGEMM: C[M,N] = A[M,K] @ B[K,N] + bias[N]   (row-major, fp32)
// 128x128 block tile, BK=8, 256 threads, 8x8 micro-tile.
// M,N multiples of 128; K multiple of 8 (true for all three calls).
// ---------------------------------------------------------------------------
__global__ __launch_bounds__(256) void sgemm_bias_kernel(
    const float* __restrict__ A, const float* __restrict__ B,
    const float* __restrict__ bias, float* __restrict__ C,
    int M, int N, int K)
{
    __shared__ float As[8][128];   // [k][m] (transposed A tile)
    __shared__ float Bs[8][128];   // [k][n]

    const int tid = threadIdx.x;
    const int bm = blockIdx.y * 128;
    const int bn = blockIdx.x * 128;

    // A tile load mapping: 128 rows x 8 k, one float4 per thread
    const int arow = tid >> 1;          // 0..127
    const int acol = (tid & 1) * 4;     // 0 or 4
    // B tile load mapping: 8 rows x 128 cols, one float4 per thread
    const int brow = tid >> 5;          // 0..7
    const int bcol = (tid & 31) * 4;    // 0..124

    const int tr = tid >> 4;            // 0..15
    const int tc = tid & 15;            // 0..15
    const int row0 = tr * 8;
    const int col0 = tc * 8;

    float acc[8][8];
    #pragma unroll
    for (int i = 0; i < 8; ++i)
        #pragma unroll
        for (int j = 0; j < 8; ++j) acc[i][j] = 0.0f;

    const float* Aptr = A + (long)(bm + arow) * K + acol;

    for (int kt = 0; kt < K; kt += 8) {
        float4 a4 = *(const float4*)(Aptr + kt);
        float4 b4 = *(const float4*)(B + (long)(kt + brow) * N + bn + bcol);

        __syncthreads();   // previous compute done before overwriting smem
        As[acol + 0][arow] = a4.x;
        As[acol + 1][arow] = a4.y;
        As[acol + 2][arow] = a4.z;
        As[acol + 3][arow] = a4.w;
        *(float4*)&Bs[brow][bcol] = b4;
        __syncthreads();

        #pragma unroll
        for (int k = 0; k < 8; ++k) {
            float4 a0 = *(float4*)&As[k][row0];
            float4 a1 = *(float4*)&As[k][row0 + 4];
            float4 b0 = *(float4*)&Bs[k][col0];
            float4 b1 = *(float4*)&Bs[k][col0 + 4];
            float ar[8] = {a0.x, a0.y, a0.z, a0.w, a1.x, a1.y, a1.z, a1.w};
            float br[8] = {b0.x, b0.y, b0.z, b0.w, b1.x, b1.y, b1.z, b1.w};
            #pragma unroll
            for (int i = 0; i < 8; ++i)
                #pragma unroll
                for (int j = 0; j < 8; ++j)
                    acc[i][j] = fmaf(ar[i], br[j], acc[i][j]);
        }
    }

    float4 bi0 = *(const float4*)(bias + bn + col0);
    float4 bi1 = *(const float4*)(bias + bn + col0 + 4);
    #pragma unroll
    for (int i = 0; i < 8; ++i) {
        float* crow = C + (long)(bm + row0 + i) * N + bn + col0;
        float4 o0 = make_float4(acc[i][0] + bi0.x, acc[i][1] + bi0.y,
                                acc[i][2] + bi0.z, acc[i][3] + bi0.w);
        float4 o1 = make_float4(acc[i][4] + bi1.x, acc[i][5] + bi1.y,
                                acc[i][6] + bi1.z, acc[i][7] + bi1.w);
        *(float4*)(crow)     = o0;
        *(float4*)(crow + 4) = o1;
    }
}

// ---------------------------------------------------------------------------
// Flash attention (fp32, online softmax).
// Grid: (S/64, H, B). 256 threads. BM=BN=64, HD=64.
// Each thread owns a 4x4 micro-tile. Softmax stats in registers,
// reduced across the 16-lane group via shfl_xor.
// smem: Qt[d][r], KP[ ][ ] (K tile d-major, then P tile r-major), Vs[c][d].
// 3 * 16KB = 48KB static shared (exactly at the limit).
// ---------------------------------------------------------------------------
__global__ __launch_bounds__(256) void attn_kernel(
    const float* __restrict__ qkv, float* __restrict__ out)
{
    __shared__ float Qt[64][64];   // [d][r]
    __shared__ float KP[64][64];   // K: [d][c]  /  P: [r][c]
    __shared__ float Vs[64][64];   // [c][d]

    const int tid  = threadIdx.x;
    const int qblk = blockIdx.x;
    const int h    = blockIdx.y;
    const int b    = blockIdx.z;

    const int tok0 = b * Sq + qblk * 64;     // first query token (global row)
    const float* qbase = qkv + h * HDq;
    const float* kbase = qkv + Dq + h * HDq;
    const float* vbase = qkv + 2 * Dq + h * HDq;

    // Load Q tile transposed: Qt[d][r]
    #pragma unroll
    for (int it = 0; it < 4; ++it) {
        int idx = tid + it * 256;            // 0..1023
        int r   = idx >> 4;                  // 0..63
        int d0  = (idx & 15) * 4;
        float4 q4 = *(const float4*)(qbase + (long)(tok0 + r) * QKVN + d0);
        Qt[d0 + 0][r] = q4.x;
        Qt[d0 + 1][r] = q4.y;
        Qt[d0 + 2][r] = q4.z;
        Qt[d0 + 3][r] = q4.w;
    }

    const int gr = tid >> 4;      // 0..15 : row group
    const int gc = tid & 15;      // 0..15 : col / hd group
    const int r0 = gr * 4;
    const int c0 = gc * 4;

    float m[4], l[4], O[4][4];
    #pragma unroll
    for (int i = 0; i < 4; ++i) {
        m[i] = -1e30f; l[i] = 0.0f;
        #pragma unroll
        for (int j = 0; j < 4; ++j) O[i][j] = 0.0f;
    }

    for (int kt = 0; kt < Sq / 64; ++kt) {
        const int ktok0 = b * Sq + kt * 64;

        // Load K tile (transposed) and V tile (direct)
        #pragma unroll
        for (int it = 0; it < 4; ++it) {
            int idx = tid + it * 256;
            int c   = idx >> 4;
            int d0  = (idx & 15) * 4;
            float4 k4 = *(const float4*)(kbase + (long)(ktok0 + c) * QKVN + d0);
            KP[d0 + 0][c] = k4.x;
            KP[d0 + 1][c] = k4.y;
            KP[d0 + 2][c] = k4.z;
            KP[d0 + 3][c] = k4.w;
            float4 v4 = *(const float4*)(vbase + (long)(ktok0 + c) * QKVN + d0);
            *(float4*)&Vs[c][d0] = v4;
        }
        __syncthreads();

        // Scores: s[i][j] = sum_d Q[r0+i][d] * K[c0+j][d]
        float s[4][4];
        #pragma unroll
        for (int i = 0; i < 4; ++i)
            #pragma unroll
            for (int j = 0; j < 4; ++j) s[i][j] = 0.0f;

        #pragma unroll 8
        for (int d = 0; d < 64; ++d) {
            float4 qv = *(float4*)&Qt[d][r0];
            float4 kv = *(float4*)&KP[d][c0];
            float qa[4] = {qv.x, qv.y, qv.z, qv.w};
            float ka[4] = {kv.x, kv.y, kv.z, kv.w};
            #pragma unroll
            for (int i = 0; i < 4; ++i)
                #pragma unroll
                for (int j = 0; j < 4; ++j)
                    s[i][j] = fmaf(qa[i], ka[j], s[i][j]);
        }

        // Online softmax update (per row), reduced over the 16-lane group
        float p[4][4];
        float alpha[4];
        #pragma unroll
        for (int i = 0; i < 4; ++i) {
            float mt = -1e30f;
            #pragma unroll
            for (int j = 0; j < 4; ++j) {
                s[i][j] *= 0.125f;                       // 1/sqrt(64)
                mt = fmaxf(mt, s[i][j]);
            }
            #pragma unroll
            for (int off = 8; off >= 1; off >>= 1)
                mt = fmaxf(mt, __shfl_xor_sync(0xffffffffu, mt, off));
            float mnew = fmaxf(m[i], mt);
            alpha[i] = __expf(m[i] - mnew);
            float rs = 0.0f;
            #pragma unroll
            for (int j = 0; j < 4; ++j) {
                p[i][j] = __expf(s[i][j] - mnew);
                rs += p[i][j];
            }
            #pragma unroll
            for (int off = 8; off >= 1; off >>= 1)
                rs += __shfl_xor_sync(0xffffffffu, rs, off);
            l[i] = l[i] * alpha[i] + rs;
            m[i] = mnew;
            #pragma unroll
            for (int j = 0; j < 4; ++j) O[i][j] *= alpha[i];
        }

        __syncthreads();   // everyone done reading KP as K
        // Store P tile: KP[r][c]
        #pragma unroll
        for (int i = 0; i < 4; ++i)
            *(float4*)&KP[r0 + i][c0] = make_float4(p[i][0], p[i][1], p[i][2], p[i][3]);
        __syncthreads();

        // O += P @ V  (thread owns rows r0..r0+3, hd cols c0..c0+3)
        #pragma unroll 8
        for (int c = 0; c < 64; ++c) {
            float4 vv = *(float4*)&Vs[c][c0];
            float va[4] = {vv.x, vv.y, vv.z, vv.w};
            float pr[4];
            #pragma unroll
            for (int i = 0; i < 4; ++i) pr[i] = KP[r0 + i][c];
            #pragma unroll
            for (int i = 0; i < 4; ++i)
                #pragma unroll
                for (int j = 0; j < 4; ++j)
                    O[i][j] = fmaf(pr[i], va[j], O[i][j]);
        }
        __syncthreads();   // before next tile overwrites KP/Vs
    }

    // Epilogue: normalize and write [B,S,D] with D index = h*64 + hd
    #pragma unroll
    for (int i = 0; i < 4; ++i) {
        float inv = 1.0f / l[i];
        float4 o4 = make_float4(O[i][0] * inv, O[i][1] * inv,
                                O[i][2] * inv, O[i][3] * inv);
        *(float4*)(out + (long)(tok0 + r0 + i) * Dq + h * HDq + c0) = o4;
    }
}

// ---------------------------------------------------------------------------
// Launch
// ---------------------------------------------------------------------------
extern "C" void kernel_launch(void* const* d_in, const int* in_sizes, int n_in,
                              void* d_out, int out_size)
{
    const float* x      = (const float*)d_in[0];  // [B,S,D]
    const float* W_qkv  = (const float*)d_in[1];  // [D, 3D]
    const float* b_qkv  = (const float*)d_in[2];  // [3D]
    const float* W_proj = (const float*)d_in[3];  // [D, D]
    const float* b_proj = (const float*)d_in[4];  // [D]
    float* outp = (float*)d_out;                  // [B,S,D]

    float* qkv;
    float* attn;
    cudaGetSymbolAddress((void**)&qkv, g_qkv);
    cudaGetSymbolAddress((void**)&attn, g_attn);

    // 1) QKV projection: [4096,1024] @ [1024,3072] + b
    {
        dim3 grid(QKVN / 128, NTOK / 128);
        sgemm_bias_kernel<<<grid, 256>>>(x, W_qkv, b_qkv, qkv, NTOK, QKVN, Dq);
    }
    // 2) Attention
    {
        dim3 grid(Sq / 64, Hq, Bq);
        attn_kernel<<<grid, 256>>>(qkv, attn);
    }
    // 3) Output projection: [4096,1024] @ [1024,1024] + b
    {
        dim3 grid(Dq / 128, NTOK / 128);
        sgemm_bias_kernel<<<grid, 256>>>(attn, W_proj, b_proj, outp, NTOK, Dq, Dq);
    }
}

// round 4
// speedup vs baseline: 1.3757x; 1.3757x over previous
#include <cuda_runtime.h>
#include <cuda_bf16.h>
#include <cstdint>

// Problem constants
#define Bq   2
#define Sq   2048
#define Dq   1024
#define Hq   16
#define HDq  64
#define NTOK (Bq * Sq)          // 4096
#define QKVN (3 * Dq)           // 3072

// Scratch (device globals: allocation-free rule)
__device__ float g_qkv[NTOK * QKVN];   // [4096][3072] : Q|K|V (fp32)
__device__ float g_attn[NTOK * Dq];    // [4096][1024] : attention output

// ---------------------------------------------------------------------------
// MMA wrappers
// ---------------------------------------------------------------------------
__device__ __forceinline__ void mma_bf16(float* c, unsigned a0, unsigned a1,
                                         unsigned a2, unsigned a3,
                                         unsigned b0, unsigned b1)
{
    asm volatile(
        "mma.sync.aligned.m16n8k16.row.col.f32.bf16.bf16.f32 "
        "{%0,%1,%2,%3}, {%4,%5,%6,%7}, {%8,%9}, {%0,%1,%2,%3};\n"
        : "+f"(c[0]), "+f"(c[1]), "+f"(c[2]), "+f"(c[3])
        : "r"(a0), "r"(a1), "r"(a2), "r"(a3), "r"(b0), "r"(b1));
}

__device__ __forceinline__ void mma_tf32(float* c, unsigned a0, unsigned a1,
                                         unsigned a2, unsigned a3,
                                         unsigned b0, unsigned b1)
{
    asm volatile(
        "mma.sync.aligned.m16n8k8.row.col.f32.tf32.tf32.f32 "
        "{%0,%1,%2,%3}, {%4,%5,%6,%7}, {%8,%9}, {%0,%1,%2,%3};\n"
        : "+f"(c[0]), "+f"(c[1]), "+f"(c[2]), "+f"(c[3])
        : "r"(a0), "r"(a1), "r"(a2), "r"(a3), "r"(b0), "r"(b1));
}

__device__ __forceinline__ float tf32r(float x)
{
    float y;
    asm("cvt.rna.tf32.f32 %0, %1;" : "=f"(y) : "f"(x));
    return y;
}

__device__ __forceinline__ unsigned pk2(__nv_bfloat16 a, __nv_bfloat16 b)
{
    return (unsigned)__bfloat16_as_ushort(a) |
           ((unsigned)__bfloat16_as_ushort(b) << 16);
}

__device__ __forceinline__ unsigned fbits(float x) { return __float_as_uint(x); }

// ---------------------------------------------------------------------------
// GEMM: C[M,N] = A[M,K] @ B[K,N] + bias, split-bf16 (3-MMA) compensation.
// Block 128x128, BK=16 (double buffered), 256 threads, warp tile 64x32.
// Smem: hi/lo bf16 tiles, A as [m][k] (stride 24 halves), B as [n][k].
// ---------------------------------------------------------------------------
#define ASTR 24   // halves per smem row (16 data + 8 pad): conflict-free frags

__global__ __launch_bounds__(256, 2) void gemm_bf16x3_kernel(
    const float* __restrict__ A, const float* __restrict__ B,
    const float* __restrict__ bias, float* __restrict__ C,
    int M, int N, int K)
{
    __shared__ __nv_bfloat16 Ahi[2][128 * ASTR];
    __shared__ __nv_bfloat16 Alo[2][128 * ASTR];
    __shared__ __nv_bfloat16 Bhi[2][128 * ASTR];
    __shared__ __nv_bfloat16 Blo[2][128 * ASTR];

    const int tid  = threadIdx.x;
    const int lane = tid & 31;
    const int wid  = tid >> 5;
    const int q    = lane >> 2;      // group id 0..7
    const int sq   = lane & 3;       // thread-in-group 0..3

    const int bm = blockIdx.y * 128;
    const int bn = blockIdx.x * 128;

    // global load mappings
    const int arow = tid >> 1;            // 0..127
    const int ak0  = (tid & 1) * 8;       // 0 or 8
    const int bkr  = tid >> 4;            // 0..15
    const int bn0  = (tid & 15) * 8;      // 0..120

    // warp tile
    const int rm = (wid & 1) * 64;
    const int cn = (wid >> 1) * 32;

    float acc[4][4][4];
    #pragma unroll
    for (int i = 0; i < 4; ++i)
        #pragma unroll
        for (int j = 0; j < 4; ++j)
            #pragma unroll
            for (int k = 0; k < 4; ++k) acc[i][j][k] = 0.0f;

    const float* Ag = A + (long)(bm + arow) * K + ak0;

    float4 pa0, pa1, pb0, pb1;

    // ---- load tile 0 ----
    pa0 = *(const float4*)(Ag);
    pa1 = *(const float4*)(Ag + 4);
    {
        const float* bg = B + (long)bkr * N + bn + bn0;
        pb0 = *(const float4*)(bg);
        pb1 = *(const float4*)(bg + 4);
    }

    // convert+store helper (written inline twice via macro)
#define STORE_TILE(BUF)                                                        \
    {                                                                          \
        float av[8] = {pa0.x, pa0.y, pa0.z, pa0.w, pa1.x, pa1.y, pa1.z, pa1.w};\
        __nv_bfloat16 h[8], l[8];                                              \
        _Pragma("unroll")                                                      \
        for (int j = 0; j < 8; ++j) {                                          \
            h[j] = __float2bfloat16(av[j]);                                    \
            l[j] = __float2bfloat16(av[j] - __bfloat162float(h[j]));           \
        }                                                                      \
        unsigned* dh = (unsigned*)&Ahi[BUF][arow * ASTR + ak0];                \
        unsigned* dl = (unsigned*)&Alo[BUF][arow * ASTR + ak0];                \
        dh[0] = pk2(h[0], h[1]); dh[1] = pk2(h[2], h[3]);                      \
        dh[2] = pk2(h[4], h[5]); dh[3] = pk2(h[6], h[7]);                      \
        dl[0] = pk2(l[0], l[1]); dl[1] = pk2(l[2], l[3]);                      \
        dl[2] = pk2(l[4], l[5]); dl[3] = pk2(l[6], l[7]);                      \
        float bv[8] = {pb0.x, pb0.y, pb0.z, pb0.w, pb1.x, pb1.y, pb1.z, pb1.w};\
        _Pragma("unroll")                                                      \
        for (int j = 0; j < 8; ++j) {                                          \
            __nv_bfloat16 bh = __float2bfloat16(bv[j]);                        \
            __nv_bfloat16 bl = __float2bfloat16(bv[j] - __bfloat162float(bh)); \
            Bhi[BUF][(bn0 + j) * ASTR + bkr] = bh;                             \
            Blo[BUF][(bn0 + j) * ASTR + bkr] = bl;                             \
        }                                                                      \
    }

    STORE_TILE(0)
    __syncthreads();

    const int nk = K >> 4;
    for (int t = 0; t < nk; ++t) {
        const int buf = t & 1;
        const bool has_next = (t + 1 < nk);
        if (has_next) {
            const float* ag = Ag + (t + 1) * 16;
            pa0 = *(const float4*)(ag);
            pa1 = *(const float4*)(ag + 4);
            const float* bg = B + (long)((t + 1) * 16 + bkr) * N + bn + bn0;
            pb0 = *(const float4*)(bg);
            pb1 = *(const float4*)(bg + 4);
        }

        // ---- compute on buf ----
        unsigned bh[4][2], bl[4][2];
        #pragma unroll
        for (int nf = 0; nf < 4; ++nf) {
            int n = cn + nf * 8 + q;
            const __nv_bfloat16* bp = &Bhi[buf][n * ASTR + 2 * sq];
            bh[nf][0] = *(const unsigned*)bp;
            bh[nf][1] = *(const unsigned*)(bp + 8);
            const __nv_bfloat16* lp = &Blo[buf][n * ASTR + 2 * sq];
            bl[nf][0] = *(const unsigned*)lp;
            bl[nf][1] = *(const unsigned*)(lp + 8);
        }
        #pragma unroll
        for (int mf = 0; mf < 4; ++mf) {
            int r = rm + mf * 16 + q;
            const __nv_bfloat16* ap = &Ahi[buf][r * ASTR + 2 * sq];
            unsigned ah0 = *(const unsigned*)ap;
            unsigned ah2 = *(const unsigned*)(ap + 8);
            unsigned ah1 = *(const unsigned*)(ap + 8 * ASTR);
            unsigned ah3 = *(const unsigned*)(ap + 8 * ASTR + 8);
            const __nv_bfloat16* lp = &Alo[buf][r * ASTR + 2 * sq];
            unsigned al0 = *(const unsigned*)lp;
            unsigned al2 = *(const unsigned*)(lp + 8);
            unsigned al1 = *(const unsigned*)(lp + 8 * ASTR);
            unsigned al3 = *(const unsigned*)(lp + 8 * ASTR + 8);
            #pragma unroll
            for (int nf = 0; nf < 4; ++nf) {
                mma_bf16(acc[mf][nf], ah0, ah1, ah2, ah3, bh[nf][0], bh[nf][1]);
                mma_bf16(acc[mf][nf], ah0, ah1, ah2, ah3, bl[nf][0], bl[nf][1]);
                mma_bf16(acc[mf][nf], al0, al1, al2, al3, bh[nf][0], bh[nf][1]);
            }
        }

        if (has_next) {
            STORE_TILE(buf ^ 1)
        }
        __syncthreads();
    }

    // ---- epilogue ----
    #pragma unroll
    for (int nf = 0; nf < 4; ++nf) {
        int c = bn + cn + nf * 8 + 2 * sq;
        float2 bi = *(const float2*)(bias + c);
        #pragma unroll
        for (int mf = 0; mf < 4; ++mf) {
            int r = bm + rm + mf * 16 + q;
            float2 o0 = make_float2(acc[mf][nf][0] + bi.x, acc[mf][nf][1] + bi.y);
            float2 o1 = make_float2(acc[mf][nf][2] + bi.x, acc[mf][nf][3] + bi.y);
            *(float2*)(C + (long)r * N + c)       = o0;
            *(float2*)(C + (long)(r + 8) * N + c) = o1;
        }
    }
#undef STORE_TILE
}

// ---------------------------------------------------------------------------
// Flash attention, tf32 mma.sync (m16n8k8), online softmax.
// Block: 128 threads (4 warps), 64 q-rows (16/warp). Grid (S/64, H, B).
// Smem (48KB exact): PS (Q then P, per-warp rows), Ks [d][c], Vs [c][d];
// all XOR-swizzled: elem (r, c) at [r*64 + (c ^ ((r&7)<<3))].
// ---------------------------------------------------------------------------
__global__ __launch_bounds__(128, 4) void attn_tf32_kernel(
    const float* __restrict__ qkv, float* __restrict__ out)
{
    __shared__ float PS[64 * 64];
    __shared__ float Ks[64 * 64];
    __shared__ float Vs[64 * 64];

    const int tid  = threadIdx.x;
    const int lane = tid & 31;
    const int wid  = tid >> 5;
    const int q    = lane >> 2;   // 0..7
    const int sq   = lane & 3;    // 0..3

    const int qblk = blockIdx.x;
    const int h    = blockIdx.y;
    const int b    = blockIdx.z;

    const int tok0 = b * Sq + qblk * 64;
    const float* qbase = qkv + h * HDq;
    const float* kbase = qkv + Dq + h * HDq;
    const float* vbase = qkv + 2 * Dq + h * HDq;

    // ---- load Q tile (scaled by 1/8, tf32) into PS, swizzled ----
    #pragma unroll
    for (int it = 0; it < 8; ++it) {
        int idx = tid + it * 128;            // 0..1023
        int r   = idx >> 4;                  // 0..63
        int d0  = (idx & 15) * 4;
        float4 v = *(const float4*)(qbase + (long)(tok0 + r) * QKVN + d0);
        int base = r * 64 + (d0 ^ ((r & 7) << 3));
        PS[base + 0] = tf32r(v.x * 0.125f);
        PS[base + 1] = tf32r(v.y * 0.125f);
        PS[base + 2] = tf32r(v.z * 0.125f);
        PS[base + 3] = tf32r(v.w * 0.125f);
    }
    __syncthreads();

    const int rl = wid * 16 + q;             // low row (tile-local)

    // ---- extract Q fragments (per-warp rows only) ----
    unsigned qf[8][4];
    #pragma unroll
    for (int kk = 0; kk < 8; ++kk) {
        int base = rl * 64 + ((kk ^ q) << 3) + sq;
        qf[kk][0] = fbits(PS[base]);
        qf[kk][1] = fbits(PS[base + 512]);
        qf[kk][2] = fbits(PS[base + 4]);
        qf[kk][3] = fbits(PS[base + 516]);
    }

    float O[8][4];
    #pragma unroll
    for (int nf = 0; nf < 8; ++nf)
        #pragma unroll
        for (int k = 0; k < 4; ++k) O[nf][k] = 0.0f;
    float m0 = -1e30f, m1 = -1e30f, l0 = 0.0f, l1 = 0.0f;

    for (int kt = 0; kt < Sq / 64; ++kt) {
        const int ktok0 = b * Sq + kt * 64;
        __syncthreads();   // previous tile's K/V reads complete
        #pragma unroll
        for (int it = 0; it < 8; ++it) {
            int idx = tid + it * 128;
            int c   = idx >> 4;
            int d0  = (idx & 15) * 4;
            float4 kv = *(const float4*)(kbase + (long)(ktok0 + c) * QKVN + d0);
            Ks[(d0 + 0) * 64 + (c ^ (((d0 + 0) & 7) << 3))] = tf32r(kv.x);
            Ks[(d0 + 1) * 64 + (c ^ (((d0 + 1) & 7) << 3))] = tf32r(kv.y);
            Ks[(d0 + 2) * 64 + (c ^ (((d0 + 2) & 7) << 3))] = tf32r(kv.z);
            Ks[(d0 + 3) * 64 + (c ^ (((d0 + 3) & 7) << 3))] = tf32r(kv.w);
            float4 vv = *(const float4*)(vbase + (long)(ktok0 + c) * QKVN + d0);
            int vb = c * 64 + (d0 ^ ((c & 7) << 3));
            float4 vt = make_float4(tf32r(vv.x), tf32r(vv.y), tf32r(vv.z), tf32r(vv.w));
            *(float4*)&Vs[vb] = vt;
        }
        __syncthreads();

        // ---- scores: sc = Q @ K^T (scaled) ----
        float sc[8][4];
        #pragma unroll
        for (int nf = 0; nf < 8; ++nf) {
            sc[nf][0] = sc[nf][1] = sc[nf][2] = sc[nf][3] = 0.0f;
            int cx = ((nf ^ sq) << 3) + q;           // c ^ (sq<<3)
            const float* p0 = Ks + sq * 64 + cx;
            const float* p1 = Ks + (sq + 4) * 64 + (cx ^ 32);
            #pragma unroll
            for (int kk = 0; kk < 8; ++kk) {
                unsigned b0 = fbits(p0[kk * 512]);
                unsigned b1 = fbits(p1[kk * 512]);
                mma_tf32(sc[nf], qf[kk][0], qf[kk][1], qf[kk][2], qf[kk][3], b0, b1);
            }
        }

        // ---- online softmax ----
        float mx0 = -1e30f, mx1 = -1e30f;
        #pragma unroll
        for (int nf = 0; nf < 8; ++nf) {
            mx0 = fmaxf(mx0, fmaxf(sc[nf][0], sc[nf][1]));
            mx1 = fmaxf(mx1, fmaxf(sc[nf][2], sc[nf][3]));
        }
        mx0 = fmaxf(mx0, __shfl_xor_sync(0xffffffffu, mx0, 1));
        mx0 = fmaxf(mx0, __shfl_xor_sync(0xffffffffu, mx0, 2));
        mx1 = fmaxf(mx1, __shfl_xor_sync(0xffffffffu, mx1, 1));
        mx1 = fmaxf(mx1, __shfl_xor_sync(0xffffffffu, mx1, 2));
        float mn0 = fmaxf(m0, mx0), mn1 = fmaxf(m1, mx1);
        float al0 = __expf(m0 - mn0), al1 = __expf(m1 - mn1);
        float s0 = 0.0f, s1 = 0.0f;
        #pragma unroll
        for (int nf = 0; nf < 8; ++nf) {
            sc[nf][0] = __expf(sc[nf][0] - mn0);
            sc[nf][1] = __expf(sc[nf][1] - mn0);
            sc[nf][2] = __expf(sc[nf][2] - mn1);
            sc[nf][3] = __expf(sc[nf][3] - mn1);
            s0 += sc[nf][0] + sc[nf][1];
            s1 += sc[nf][2] + sc[nf][3];
        }
        s0 += __shfl_xor_sync(0xffffffffu, s0, 1);
        s0 += __shfl_xor_sync(0xffffffffu, s0, 2);
        s1 += __shfl_xor_sync(0xffffffffu, s1, 1);
        s1 += __shfl_xor_sync(0xffffffffu, s1, 2);
        l0 = l0 * al0 + s0;  m0 = mn0;
        l1 = l1 * al1 + s1;  m1 = mn1;
        #pragma unroll
        for (int nf = 0; nf < 8; ++nf) {
            O[nf][0] *= al0; O[nf][1] *= al0;
            O[nf][2] *= al1; O[nf][3] *= al1;
        }

        // ---- store P (tf32) to PS (own warp's rows only) ----
        #pragma unroll
        for (int nf = 0; nf < 8; ++nf) {
            int a0 = rl * 64 + ((nf ^ q) << 3) + 2 * sq;
            *(float2*)&PS[a0]       = make_float2(tf32r(sc[nf][0]), tf32r(sc[nf][1]));
            *(float2*)&PS[a0 + 512] = make_float2(tf32r(sc[nf][2]), tf32r(sc[nf][3]));
        }
        __syncwarp();

        // ---- preload P fragments ----
        unsigned pf[8][4];
        #pragma unroll
        for (int kf = 0; kf < 8; ++kf) {
            int pb = rl * 64 + ((kf ^ q) << 3) + sq;
            pf[kf][0] = fbits(PS[pb]);
            pf[kf][1] = fbits(PS[pb + 512]);
            pf[kf][2] = fbits(PS[pb + 4]);
            pf[kf][3] = fbits(PS[pb + 516]);
        }

        // ---- O += P @ V ----
        #pragma unroll
        for (int nf = 0; nf < 8; ++nf) {
            int dx = ((nf ^ sq) << 3) + q;           // d ^ (sq<<3)
            const float* p0 = Vs + sq * 64 + dx;
            const float* p1 = Vs + (sq + 4) * 64 + (dx ^ 32);
            #pragma unroll
            for (int kf = 0; kf < 8; ++kf) {
                unsigned b0 = fbits(p0[kf * 512]);
                unsigned b1 = fbits(p1[kf * 512]);
                mma_tf32(O[nf], pf[kf][0], pf[kf][1], pf[kf][2], pf[kf][3], b0, b1);
            }
        }
    }

    // ---- epilogue ----
    float inv0 = 1.0f / l0, inv1 = 1.0f / l1;
    #pragma unroll
    for (int nf = 0; nf < 8; ++nf) {
        int c = h * HDq + nf * 8 + 2 * sq;
        float2 o0 = make_float2(O[nf][0] * inv0, O[nf][1] * inv0);
        float2 o1 = make_float2(O[nf][2] * inv1, O[nf][3] * inv1);
        *(float2*)(out + (long)(tok0 + rl) * Dq + c)     = o0;
        *(float2*)(out + (long)(tok0 + rl + 8) * Dq + c) = o1;
    }
}

// ---------------------------------------------------------------------------
// Launch
// ---------------------------------------------------------------------------
extern "C" void kernel_launch(void* const* d_in, const int* in_sizes, int n_in,
                              void* d_out, int out_size)
{
    const float* x      = (const float*)d_in[0];  // [B,S,D]
    const float* W_qkv  = (const float*)d_in[1];  // [D, 3D]
    const float* b_qkv  = (const float*)d_in[2];  // [3D]
    const float* W_proj = (const float*)d_in[3];  // [D, D]
    const float* b_proj = (const float*)d_in[4];  // [D]
    float* outp = (float*)d_out;                  // [B,S,D]

    float* qkv;
    float* attn;
    cudaGetSymbolAddress((void**)&qkv, g_qkv);
    cudaGetSymbolAddress((void**)&attn, g_attn);

    // 1) QKV projection: [4096,1024] @ [1024,3072] + b
    {
        dim3 grid(QKVN / 128, NTOK / 128);
        gemm_bf16x3_kernel<<<grid, 256>>>(x, W_qkv, b_qkv, qkv, NTOK, QKVN, Dq);
    }
    // 2) Attention
    {
        dim3 grid(Sq / 64, Hq, Bq);
        attn_tf32_kernel<<<grid, 128>>>(qkv, attn);
    }
    // 3) Output projection: [4096,1024] @ [1024,1024] + b
    {
        dim3 grid(Dq / 128, NTOK / 128);
        gemm_bf16x3_kernel<<<grid, 256>>>(attn, W_proj, b_proj, outp, NTOK, Dq, Dq);
    }
}

// round 9
// speedup vs baseline: 2.2059x; 1.6035x over previous
#include <cuda_runtime.h>
#include <cuda_bf16.h>
#include <cstdint>

// Problem constants
#define Bq   2
#define Sq   2048
#define Dq   1024
#define Hq   16
#define HDq  64
#define NTOK (Bq * Sq)          // 4096
#define QKVN (3 * Dq)           // 3072

// Scratch (device globals: allocation-free rule)
__device__ float g_qkv[NTOK * QKVN];                 // fp32 Q|K|V for attention
__device__ __nv_bfloat16 g_xhi[NTOK * Dq];           // x split
__device__ __nv_bfloat16 g_xlo[NTOK * Dq];
__device__ __nv_bfloat16 g_wqkvt_hi[QKVN * Dq];      // W_qkv^T [N,K]
__device__ __nv_bfloat16 g_wqkvt_lo[QKVN * Dq];
__device__ __nv_bfloat16 g_wprot_hi[Dq * Dq];        // W_proj^T [N,K]
__device__ __nv_bfloat16 g_wprot_lo[Dq * Dq];
__device__ __nv_bfloat16 g_ahi[NTOK * Dq];           // attention out split
__device__ __nv_bfloat16 g_alo[NTOK * Dq];

// ---------------------------------------------------------------------------
// Helpers
// ---------------------------------------------------------------------------
__device__ __forceinline__ uint32_t smem_u32(const void* p)
{
    uint32_t a;
    asm("{ .reg .u64 t; cvta.to.shared.u64 t, %1; cvt.u32.u64 %0, t; }"
        : "=r"(a) : "l"(p));
    return a;
}

#define SWZ(x) ((x) ^ (((x) >> 3) & 0x70))

__device__ __forceinline__ void cp_async16(uint32_t dst, const void* src)
{
    asm volatile("cp.async.cg.shared.global [%0], [%1], 16;" :: "r"(dst), "l"(src));
}
#define CP_COMMIT() asm volatile("cp.async.commit_group;" ::: "memory")

__device__ __forceinline__ void ldsm_x4(unsigned& r0, unsigned& r1,
                                        unsigned& r2, unsigned& r3, uint32_t a)
{
    asm volatile("ldmatrix.sync.aligned.m8n8.x4.shared.b16 {%0,%1,%2,%3}, [%4];"
                 : "=r"(r0), "=r"(r1), "=r"(r2), "=r"(r3) : "r"(a));
}

__device__ __forceinline__ void mma_bf16(float* c, unsigned a0, unsigned a1,
                                         unsigned a2, unsigned a3,
                                         unsigned b0, unsigned b1)
{
    asm volatile(
        "mma.sync.aligned.m16n8k16.row.col.f32.bf16.bf16.f32 "
        "{%0,%1,%2,%3}, {%4,%5,%6,%7}, {%8,%9}, {%0,%1,%2,%3};\n"
        : "+f"(c[0]), "+f"(c[1]), "+f"(c[2]), "+f"(c[3])
        : "r"(a0), "r"(a1), "r"(a2), "r"(a3), "r"(b0), "r"(b1));
}

__device__ __forceinline__ void mma_tf32(float* c, unsigned a0, unsigned a1,
                                         unsigned a2, unsigned a3,
                                         unsigned b0, unsigned b1)
{
    asm volatile(
        "mma.sync.aligned.m16n8k8.row.col.f32.tf32.tf32.f32 "
        "{%0,%1,%2,%3}, {%4,%5,%6,%7}, {%8,%9}, {%0,%1,%2,%3};\n"
        : "+f"(c[0]), "+f"(c[1]), "+f"(c[2]), "+f"(c[3])
        : "r"(a0), "r"(a1), "r"(a2), "r"(a3), "r"(b0), "r"(b1));
}
__device__ __forceinline__ float tf32r(float x)
{
    float y;
    asm("cvt.rna.tf32.f32 %0, %1;" : "=f"(y) : "f"(x));
    return y;
}
__device__ __forceinline__ unsigned fbits(float x) { return __float_as_uint(x); }

__device__ __forceinline__ void split_bf16(float v, __nv_bfloat16& h, __nv_bfloat16& l)
{
    h = __float2bfloat16(v);
    l = __float2bfloat16(v - __bfloat162float(h));
}

// ---------------------------------------------------------------------------
// Elementwise split: fp32 [n] -> hi/lo bf16
// ---------------------------------------------------------------------------
__global__ __launch_bounds__(256) void conv_split_kernel(
    const float* __restrict__ in, __nv_bfloat16* __restrict__ hi,
    __nv_bfloat16* __restrict__ lo, int n)
{
    int i = (blockIdx.x * 256 + threadIdx.x) * 4;
    if (i >= n) return;
    float4 v = *(const float4*)(in + i);
    __nv_bfloat16 h[4], l[4];
    split_bf16(v.x, h[0], l[0]);
    split_bf16(v.y, h[1], l[1]);
    split_bf16(v.z, h[2], l[2]);
    split_bf16(v.w, h[3], l[3]);
    *(__nv_bfloat162*)(hi + i)     = __nv_bfloat162(h[0], h[1]);
    *(__nv_bfloat162*)(hi + i + 2) = __nv_bfloat162(h[2], h[3]);
    *(__nv_bfloat162*)(lo + i)     = __nv_bfloat162(l[0], l[1]);
    *(__nv_bfloat162*)(lo + i + 2) = __nv_bfloat162(l[2], l[3]);
}

// ---------------------------------------------------------------------------
// Transpose + split: W [K,N] fp32 -> Wt hi/lo bf16 [N,K]
// ---------------------------------------------------------------------------
__global__ __launch_bounds__(256) void conv_wt_kernel(
    const float* __restrict__ W, __nv_bfloat16* __restrict__ Thi,
    __nv_bfloat16* __restrict__ Tlo, int K, int N)
{
    __shared__ float t[32][33];
    const int bx = blockIdx.x * 32;   // N offset
    const int by = blockIdx.y * 32;   // K offset
    const int tx = threadIdx.x & 31;
    const int ty = threadIdx.x >> 5;  // 0..7
    #pragma unroll
    for (int i = 0; i < 4; ++i)
        t[ty + i * 8][tx] = W[(long)(by + ty + i * 8) * N + bx + tx];
    __syncthreads();
    #pragma unroll
    for (int i = 0; i < 4; ++i) {
        int n = bx + ty + i * 8;
        int k = by + tx;
        float v = t[tx][ty + i * 8];
        __nv_bfloat16 h, l;
        split_bf16(v, h, l);
        Thi[(long)n * K + k] = h;
        Tlo[(long)n * K + k] = l;
    }
}

// ---------------------------------------------------------------------------
// GEMM: C[M,N] = A[M,K] @ Bt[N,K]^T + bias, split-bf16 3-MMA, mma.sync.
// Tile 128x64, BK=64, SW128 smem, cp.async double buffer, ldmatrix frags.
// 256 threads = 8 warps, warp grid 4(m) x 2(n), warp tile 32x32.
// Dyn smem: 2 stages * (A 32KB + B 16KB) = 96KB.
// ---------------------------------------------------------------------------
#define AHI_OFF 0
#define ALO_OFF 16384
#define BHI_OFF 32768
#define BLO_OFF 40960
#define STG_SZ  49152

__global__ __launch_bounds__(256, 2) void gemm_mma_kernel(
    const __nv_bfloat16* __restrict__ Ahi, const __nv_bfloat16* __restrict__ Alo,
    const __nv_bfloat16* __restrict__ Bhi, const __nv_bfloat16* __restrict__ Blo,
    const float* __restrict__ bias, float* __restrict__ C,
    int M, int N, int K)
{
    extern __shared__ char smem[];
    const uint32_t sbase = smem_u32(smem);

    const int tid  = threadIdx.x;
    const int lane = tid & 31;
    const int wid  = tid >> 5;
    const int wm   = (wid & 3) * 32;      // warp row offset in tile
    const int wn   = (wid >> 2) * 32;     // warp col offset in tile

    // ---- global load mapping ----
    const long rowA = blockIdx.y * 128 + (tid >> 1);
    const int  ac0  = (tid & 1) * 4;                    // chunk base (16B units)
    const long rowB = blockIdx.x * 64 + (tid >> 2);
    const int  bc0  = (tid & 3) * 2;

    const __nv_bfloat16* pAh = Ahi + rowA * K + ac0 * 8;
    const __nv_bfloat16* pAl = Alo + rowA * K + ac0 * 8;
    const __nv_bfloat16* pBh = Bhi + rowB * K + bc0 * 8;
    const __nv_bfloat16* pBl = Blo + rowB * K + bc0 * 8;

    uint32_t aswz[4], bswz[2];
    #pragma unroll
    for (int j = 0; j < 4; ++j)
        aswz[j] = SWZ((tid >> 1) * 128 + (ac0 + j) * 16);
    #pragma unroll
    for (int j = 0; j < 2; ++j)
        bswz[j] = SWZ((tid >> 2) * 128 + (bc0 + j) * 16);

    auto load_chunk = [&](int ck, int s) {
        const uint32_t base = sbase + s * STG_SZ;
        const long go = (long)ck * 64;
        #pragma unroll
        for (int j = 0; j < 4; ++j) {
            cp_async16(base + AHI_OFF + aswz[j], pAh + go + j * 8);
            cp_async16(base + ALO_OFF + aswz[j], pAl + go + j * 8);
        }
        #pragma unroll
        for (int j = 0; j < 2; ++j) {
            cp_async16(base + BHI_OFF + bswz[j], pBh + go + j * 8);
            cp_async16(base + BLO_OFF + bswz[j], pBl + go + j * 8);
        }
    };

    // ---- ldmatrix lane mapping ----
    const int a_row = (lane & 7) + ((lane >> 3) & 1) * 8;
    const int a_kc  = lane >> 4;                          // 0/1
    const int b_row = (lane & 7) + ((lane >> 4) & 1) * 8;
    const int b_kc  = (lane >> 3) & 1;

    const int arow0 = (wm + a_row) * 128;        // mf=0
    const int arow1 = (wm + 16 + a_row) * 128;   // mf=1
    const int brow0 = (wn + b_row) * 128;        // nf2=0
    const int brow1 = (wn + 16 + b_row) * 128;   // nf2=1

    float acc[2][4][4];
    #pragma unroll
    for (int i = 0; i < 2; ++i)
        #pragma unroll
        for (int j = 0; j < 4; ++j)
            #pragma unroll
            for (int k = 0; k < 4; ++k) acc[i][j][k] = 0.0f;

    load_chunk(0, 0);
    CP_COMMIT();

    const int nk = K / 64;
    for (int t = 0; t < nk; ++t) {
        const int s = t & 1;
        const bool has_next = (t + 1 < nk);
        if (has_next) {
            load_chunk(t + 1, s ^ 1);
            CP_COMMIT();
            asm volatile("cp.async.wait_group 1;" ::: "memory");
        } else {
            asm volatile("cp.async.wait_group 0;" ::: "memory");
        }
        __syncthreads();

        const uint32_t sb = sbase + s * STG_SZ;
        #pragma unroll
        for (int ks = 0; ks < 4; ++ks) {
            const int akc = ks * 2 + a_kc;
            const int bkc = ks * 2 + b_kc;
            unsigned ah0[4], ah1[4], al0[4], al1[4];
            unsigned bh0[4], bh1[4], bl0[4], bl1[4];
            ldsm_x4(ah0[0], ah0[1], ah0[2], ah0[3], sb + AHI_OFF + SWZ(arow0 + akc * 16));
            ldsm_x4(ah1[0], ah1[1], ah1[2], ah1[3], sb + AHI_OFF + SWZ(arow1 + akc * 16));
            ldsm_x4(al0[0], al0[1], al0[2], al0[3], sb + ALO_OFF + SWZ(arow0 + akc * 16));
            ldsm_x4(al1[0], al1[1], al1[2], al1[3], sb + ALO_OFF + SWZ(arow1 + akc * 16));
            ldsm_x4(bh0[0], bh0[1], bh0[2], bh0[3], sb + BHI_OFF + SWZ(brow0 + bkc * 16));
            ldsm_x4(bh1[0], bh1[1], bh1[2], bh1[3], sb + BHI_OFF + SWZ(brow1 + bkc * 16));
            ldsm_x4(bl0[0], bl0[1], bl0[2], bl0[3], sb + BLO_OFF + SWZ(brow0 + bkc * 16));
            ldsm_x4(bl1[0], bl1[1], bl1[2], bl1[3], sb + BLO_OFF + SWZ(brow1 + bkc * 16));

            #pragma unroll
            for (int mf = 0; mf < 2; ++mf) {
                unsigned* ah = mf ? ah1 : ah0;
                unsigned* al = mf ? al1 : al0;
                #pragma unroll
                for (int nf2 = 0; nf2 < 2; ++nf2) {
                    unsigned* bh = nf2 ? bh1 : bh0;
                    unsigned* bl = nf2 ? bl1 : bl0;
                    #pragma unroll
                    for (int sub = 0; sub < 2; ++sub) {
                        float* c = acc[mf][nf2 * 2 + sub];
                        mma_bf16(c, ah[0], ah[1], ah[2], ah[3], bh[sub*2], bh[sub*2+1]);
                        mma_bf16(c, ah[0], ah[1], ah[2], ah[3], bl[sub*2], bl[sub*2+1]);
                        mma_bf16(c, al[0], al[1], al[2], al[3], bh[sub*2], bh[sub*2+1]);
                    }
                }
            }
        }
        __syncthreads();
    }

    // ---- epilogue ----
    const int gr = lane >> 2;         // 0..7
    const int gc = (lane & 3) * 2;
    #pragma unroll
    for (int mf = 0; mf < 2; ++mf) {
        #pragma unroll
        for (int nf = 0; nf < 4; ++nf) {
            int col = blockIdx.x * 64 + wn + nf * 8 + gc;
            float2 bi = *(const float2*)(bias + col);
            int row = blockIdx.y * 128 + wm + mf * 16 + gr;
            float* c0 = C + (long)row * N + col;
            float* c1 = C + (long)(row + 8) * N + col;
            *(float2*)c0 = make_float2(acc[mf][nf][0] + bi.x, acc[mf][nf][1] + bi.y);
            *(float2*)c1 = make_float2(acc[mf][nf][2] + bi.x, acc[mf][nf][3] + bi.y);
        }
    }
}

// ---------------------------------------------------------------------------
// Flash attention, tf32 mma.sync, online softmax (R4 core).
// Epilogue writes hi/lo bf16 split for the proj GEMM.
// ---------------------------------------------------------------------------
__global__ __launch_bounds__(128, 4) void attn_tf32_kernel(
    const float* __restrict__ qkv,
    __nv_bfloat16* __restrict__ ohi, __nv_bfloat16* __restrict__ olo)
{
    __shared__ float PS[64 * 64];
    __shared__ float Ks[64 * 64];
    __shared__ float Vs[64 * 64];

    const int tid  = threadIdx.x;
    const int lane = tid & 31;
    const int wid  = tid >> 5;
    const int q    = lane >> 2;
    const int sq   = lane & 3;

    const int qblk = blockIdx.x;
    const int h    = blockIdx.y;
    const int b    = blockIdx.z;

    const int tok0 = b * Sq + qblk * 64;
    const float* qbase = qkv + h * HDq;
    const float* kbase = qkv + Dq + h * HDq;
    const float* vbase = qkv + 2 * Dq + h * HDq;

    #pragma unroll
    for (int it = 0; it < 8; ++it) {
        int idx = tid + it * 128;
        int r   = idx >> 4;
        int d0  = (idx & 15) * 4;
        float4 v = *(const float4*)(qbase + (long)(tok0 + r) * QKVN + d0);
        int base = r * 64 + (d0 ^ ((r & 7) << 3));
        PS[base + 0] = tf32r(v.x * 0.125f);
        PS[base + 1] = tf32r(v.y * 0.125f);
        PS[base + 2] = tf32r(v.z * 0.125f);
        PS[base + 3] = tf32r(v.w * 0.125f);
    }
    __syncthreads();

    const int rl = wid * 16 + q;

    unsigned qf[8][4];
    #pragma unroll
    for (int kk = 0; kk < 8; ++kk) {
        int base = rl * 64 + ((kk ^ q) << 3) + sq;
        qf[kk][0] = fbits(PS[base]);
        qf[kk][1] = fbits(PS[base + 512]);
        qf[kk][2] = fbits(PS[base + 4]);
        qf[kk][3] = fbits(PS[base + 516]);
    }

    float O[8][4];
    #pragma unroll
    for (int nf = 0; nf < 8; ++nf)
        #pragma unroll
        for (int k = 0; k < 4; ++k) O[nf][k] = 0.0f;
    float m0 = -1e30f, m1 = -1e30f, l0 = 0.0f, l1 = 0.0f;

    for (int kt = 0; kt < Sq / 64; ++kt) {
        const int ktok0 = b * Sq + kt * 64;
        __syncthreads();
        #pragma unroll
        for (int it = 0; it < 8; ++it) {
            int idx = tid + it * 128;
            int c   = idx >> 4;
            int d0  = (idx & 15) * 4;
            float4 kv = *(const float4*)(kbase + (long)(ktok0 + c) * QKVN + d0);
            Ks[(d0 + 0) * 64 + (c ^ (((d0 + 0) & 7) << 3))] = tf32r(kv.x);
            Ks[(d0 + 1) * 64 + (c ^ (((d0 + 1) & 7) << 3))] = tf32r(kv.y);
            Ks[(d0 + 2) * 64 + (c ^ (((d0 + 2) & 7) << 3))] = tf32r(kv.z);
            Ks[(d0 + 3) * 64 + (c ^ (((d0 + 3) & 7) << 3))] = tf32r(kv.w);
            float4 vv = *(const float4*)(vbase + (long)(ktok0 + c) * QKVN + d0);
            int vb = c * 64 + (d0 ^ ((c & 7) << 3));
            float4 vt = make_float4(tf32r(vv.x), tf32r(vv.y), tf32r(vv.z), tf32r(vv.w));
            *(float4*)&Vs[vb] = vt;
        }
        __syncthreads();

        float sc[8][4];
        #pragma unroll
        for (int nf = 0; nf < 8; ++nf) {
            sc[nf][0] = sc[nf][1] = sc[nf][2] = sc[nf][3] = 0.0f;
            int cx = ((nf ^ sq) << 3) + q;
            const float* p0 = Ks + sq * 64 + cx;
            const float* p1 = Ks + (sq + 4) * 64 + (cx ^ 32);
            #pragma unroll
            for (int kk = 0; kk < 8; ++kk) {
                unsigned b0 = fbits(p0[kk * 512]);
                unsigned b1 = fbits(p1[kk * 512]);
                mma_tf32(sc[nf], qf[kk][0], qf[kk][1], qf[kk][2], qf[kk][3], b0, b1);
            }
        }

        float mx0 = -1e30f, mx1 = -1e30f;
        #pragma unroll
        for (int nf = 0; nf < 8; ++nf) {
            mx0 = fmaxf(mx0, fmaxf(sc[nf][0], sc[nf][1]));
            mx1 = fmaxf(mx1, fmaxf(sc[nf][2], sc[nf][3]));
        }
        mx0 = fmaxf(mx0, __shfl_xor_sync(0xffffffffu, mx0, 1));
        mx0 = fmaxf(mx0, __shfl_xor_sync(0xffffffffu, mx0, 2));
        mx1 = fmaxf(mx1, __shfl_xor_sync(0xffffffffu, mx1, 1));
        mx1 = fmaxf(mx1, __shfl_xor_sync(0xffffffffu, mx1, 2));
        float mn0 = fmaxf(m0, mx0), mn1 = fmaxf(m1, mx1);
        float al0 = __expf(m0 - mn0), al1 = __expf(m1 - mn1);
        float s0 = 0.0f, s1 = 0.0f;
        #pragma unroll
        for (int nf = 0; nf < 8; ++nf) {
            sc[nf][0] = __expf(sc[nf][0] - mn0);
            sc[nf][1] = __expf(sc[nf][1] - mn0);
            sc[nf][2] = __expf(sc[nf][2] - mn1);
            sc[nf][3] = __expf(sc[nf][3] - mn1);
            s0 += sc[nf][0] + sc[nf][1];
            s1 += sc[nf][2] + sc[nf][3];
        }
        s0 += __shfl_xor_sync(0xffffffffu, s0, 1);
        s0 += __shfl_xor_sync(0xffffffffu, s0, 2);
        s1 += __shfl_xor_sync(0xffffffffu, s1, 1);
        s1 += __shfl_xor_sync(0xffffffffu, s1, 2);
        l0 = l0 * al0 + s0;  m0 = mn0;
        l1 = l1 * al1 + s1;  m1 = mn1;
        #pragma unroll
        for (int nf = 0; nf < 8; ++nf) {
            O[nf][0] *= al0; O[nf][1] *= al0;
            O[nf][2] *= al1; O[nf][3] *= al1;
        }

        #pragma unroll
        for (int nf = 0; nf < 8; ++nf) {
            int a0 = rl * 64 + ((nf ^ q) << 3) + 2 * sq;
            *(float2*)&PS[a0]       = make_float2(tf32r(sc[nf][0]), tf32r(sc[nf][1]));
            *(float2*)&PS[a0 + 512] = make_float2(tf32r(sc[nf][2]), tf32r(sc[nf][3]));
        }
        __syncwarp();

        unsigned pf[8][4];
        #pragma unroll
        for (int kf = 0; kf < 8; ++kf) {
            int pb = rl * 64 + ((kf ^ q) << 3) + sq;
            pf[kf][0] = fbits(PS[pb]);
            pf[kf][1] = fbits(PS[pb + 512]);
            pf[kf][2] = fbits(PS[pb + 4]);
            pf[kf][3] = fbits(PS[pb + 516]);
        }

        #pragma unroll
        for (int nf = 0; nf < 8; ++nf) {
            int dx = ((nf ^ sq) << 3) + q;
            const float* p0 = Vs + sq * 64 + dx;
            const float* p1 = Vs + (sq + 4) * 64 + (dx ^ 32);
            #pragma unroll
            for (int kf = 0; kf < 8; ++kf) {
                unsigned b0 = fbits(p0[kf * 512]);
                unsigned b1 = fbits(p1[kf * 512]);
                mma_tf32(O[nf], pf[kf][0], pf[kf][1], pf[kf][2], pf[kf][3], b0, b1);
            }
        }
    }

    float inv0 = 1.0f / l0, inv1 = 1.0f / l1;
    #pragma unroll
    for (int nf = 0; nf < 8; ++nf) {
        int c = h * HDq + nf * 8 + 2 * sq;
        long i0 = (long)(tok0 + rl) * Dq + c;
        long i1 = (long)(tok0 + rl + 8) * Dq + c;
        __nv_bfloat16 h0, l0b, h1, l1b;
        split_bf16(O[nf][0] * inv0, h0, l0b);
        split_bf16(O[nf][1] * inv0, h1, l1b);
        *(__nv_bfloat162*)(ohi + i0) = __nv_bfloat162(h0, h1);
        *(__nv_bfloat162*)(olo + i0) = __nv_bfloat162(l0b, l1b);
        split_bf16(O[nf][2] * inv1, h0, l0b);
        split_bf16(O[nf][3] * inv1, h1, l1b);
        *(__nv_bfloat162*)(ohi + i1) = __nv_bfloat162(h0, h1);
        *(__nv_bfloat162*)(olo + i1) = __nv_bfloat162(l0b, l1b);
    }
}

// ---------------------------------------------------------------------------
// Launch
// ---------------------------------------------------------------------------
extern "C" void kernel_launch(void* const* d_in, const int* in_sizes, int n_in,
                              void* d_out, int out_size)
{
    const float* x      = (const float*)d_in[0];
    const float* W_qkv  = (const float*)d_in[1];
    const float* b_qkv  = (const float*)d_in[2];
    const float* W_proj = (const float*)d_in[3];
    const float* b_proj = (const float*)d_in[4];
    float* outp = (float*)d_out;

    float *qkv;
    __nv_bfloat16 *xhi, *xlo, *wqh, *wql, *wph, *wpl, *ahi, *alo;
    cudaGetSymbolAddress((void**)&qkv, g_qkv);
    cudaGetSymbolAddress((void**)&xhi, g_xhi);
    cudaGetSymbolAddress((void**)&xlo, g_xlo);
    cudaGetSymbolAddress((void**)&wqh, g_wqkvt_hi);
    cudaGetSymbolAddress((void**)&wql, g_wqkvt_lo);
    cudaGetSymbolAddress((void**)&wph, g_wprot_hi);
    cudaGetSymbolAddress((void**)&wpl, g_wprot_lo);
    cudaGetSymbolAddress((void**)&ahi, g_ahi);
    cudaGetSymbolAddress((void**)&alo, g_alo);

    cudaFuncSetAttribute(gemm_mma_kernel,
                         cudaFuncAttributeMaxDynamicSharedMemorySize, 2 * STG_SZ);

    // 0) precision splits
    conv_split_kernel<<<(NTOK * Dq) / 1024, 256>>>(x, xhi, xlo, NTOK * Dq);
    {
        dim3 grid(QKVN / 32, Dq / 32);
        conv_wt_kernel<<<grid, 256>>>(W_qkv, wqh, wql, Dq, QKVN);
    }
    {
        dim3 grid(Dq / 32, Dq / 32);
        conv_wt_kernel<<<grid, 256>>>(W_proj, wph, wpl, Dq, Dq);
    }

    // 1) QKV projection: [4096,1024] @ [1024,3072] + b
    {
        dim3 grid(QKVN / 64, NTOK / 128);
        gemm_mma_kernel<<<grid, 256, 2 * STG_SZ>>>(xhi, xlo, wqh, wql, b_qkv, qkv,
                                                   NTOK, QKVN, Dq);
    }
    // 2) Attention (tf32), writes hi/lo split
    {
        dim3 grid(Sq / 64, Hq, Bq);
        attn_tf32_kernel<<<grid, 128>>>(qkv, ahi, alo);
    }
    // 3) Output projection: [4096,1024] @ [1024,1024] + b
    {
        dim3 grid(Dq / 64, NTOK / 128);
        gemm_mma_kernel<<<grid, 256, 2 * STG_SZ>>>(ahi, alo, wph, wpl, b_proj, outp,
                                                   NTOK, Dq, Dq);
    }
}

// round 12
// speedup vs baseline: 2.6718x; 1.2112x over previous
#include <cuda_runtime.h>
#include <cuda_bf16.h>
#include <cuda_fp16.h>
#include <cstdint>

// Problem constants
#define Bq   2
#define Sq   2048
#define Dq   1024
#define Hq   16
#define HDq  64
#define NTOK (Bq * Sq)          // 4096
#define QKVN (3 * Dq)           // 3072

// Scratch (device globals: allocation-free rule)
__device__ float g_qkv[NTOK * QKVN];                 // fp32 Q|K|V for attention
__device__ __nv_bfloat16 g_xhi[NTOK * Dq];           // x split
__device__ __nv_bfloat16 g_xlo[NTOK * Dq];
__device__ __nv_bfloat16 g_wqkvt_hi[QKVN * Dq];      // W_qkv^T [N,K]
__device__ __nv_bfloat16 g_wqkvt_lo[QKVN * Dq];
__device__ __nv_bfloat16 g_wprot_hi[Dq * Dq];        // W_proj^T [N,K]
__device__ __nv_bfloat16 g_wprot_lo[Dq * Dq];
__device__ __nv_bfloat16 g_ahi[NTOK * Dq];           // attention out split
__device__ __nv_bfloat16 g_alo[NTOK * Dq];

// ---------------------------------------------------------------------------
// Helpers
// ---------------------------------------------------------------------------
__device__ __forceinline__ uint32_t smem_u32(const void* p)
{
    uint32_t a;
    asm("{ .reg .u64 t; cvta.to.shared.u64 t, %1; cvt.u32.u64 %0, t; }"
        : "=r"(a) : "l"(p));
    return a;
}

#define SWZ(x) ((x) ^ (((x) >> 3) & 0x70))

__device__ __forceinline__ void cp_async16(uint32_t dst, const void* src)
{
    asm volatile("cp.async.cg.shared.global [%0], [%1], 16;" :: "r"(dst), "l"(src));
}
#define CP_COMMIT() asm volatile("cp.async.commit_group;" ::: "memory")

__device__ __forceinline__ void ldsm_x4(unsigned& r0, unsigned& r1,
                                        unsigned& r2, unsigned& r3, uint32_t a)
{
    asm volatile("ldmatrix.sync.aligned.m8n8.x4.shared.b16 {%0,%1,%2,%3}, [%4];"
                 : "=r"(r0), "=r"(r1), "=r"(r2), "=r"(r3) : "r"(a));
}

__device__ __forceinline__ void ldsm_x4_t(unsigned& r0, unsigned& r1,
                                          unsigned& r2, unsigned& r3, uint32_t a)
{
    asm volatile("ldmatrix.sync.aligned.m8n8.x4.trans.shared.b16 {%0,%1,%2,%3}, [%4];"
                 : "=r"(r0), "=r"(r1), "=r"(r2), "=r"(r3) : "r"(a));
}

__device__ __forceinline__ void mma_bf16(float* c, unsigned a0, unsigned a1,
                                         unsigned a2, unsigned a3,
                                         unsigned b0, unsigned b1)
{
    asm volatile(
        "mma.sync.aligned.m16n8k16.row.col.f32.bf16.bf16.f32 "
        "{%0,%1,%2,%3}, {%4,%5,%6,%7}, {%8,%9}, {%0,%1,%2,%3};\n"
        : "+f"(c[0]), "+f"(c[1]), "+f"(c[2]), "+f"(c[3])
        : "r"(a0), "r"(a1), "r"(a2), "r"(a3), "r"(b0), "r"(b1));
}

__device__ __forceinline__ void mma_f16(float* c, unsigned a0, unsigned a1,
                                        unsigned a2, unsigned a3,
                                        unsigned b0, unsigned b1)
{
    asm volatile(
        "mma.sync.aligned.m16n8k16.row.col.f32.f16.f16.f32 "
        "{%0,%1,%2,%3}, {%4,%5,%6,%7}, {%8,%9}, {%0,%1,%2,%3};\n"
        : "+f"(c[0]), "+f"(c[1]), "+f"(c[2]), "+f"(c[3])
        : "r"(a0), "r"(a1), "r"(a2), "r"(a3), "r"(b0), "r"(b1));
}

__device__ __forceinline__ void mma_tf32(float* c, unsigned a0, unsigned a1,
                                         unsigned a2, unsigned a3,
                                         unsigned b0, unsigned b1)
{
    asm volatile(
        "mma.sync.aligned.m16n8k8.row.col.f32.tf32.tf32.f32 "
        "{%0,%1,%2,%3}, {%4,%5,%6,%7}, {%8,%9}, {%0,%1,%2,%3};\n"
        : "+f"(c[0]), "+f"(c[1]), "+f"(c[2]), "+f"(c[3])
        : "r"(a0), "r"(a1), "r"(a2), "r"(a3), "r"(b0), "r"(b1));
}
__device__ __forceinline__ float tf32r(float x)
{
    float y;
    asm("cvt.rna.tf32.f32 %0, %1;" : "=f"(y) : "f"(x));
    return y;
}
__device__ __forceinline__ unsigned fbits(float x) { return __float_as_uint(x); }

// pack two fp32 -> fp16x2 (lo = second PTX operand)
__device__ __forceinline__ unsigned pack_f16x2(float hi, float lo)
{
    unsigned d;
    asm("cvt.rn.f16x2.f32 %0, %1, %2;" : "=r"(d) : "f"(hi), "f"(lo));
    return d;
}

__device__ __forceinline__ void split_bf16(float v, __nv_bfloat16& h, __nv_bfloat16& l)
{
    h = __float2bfloat16(v);
    l = __float2bfloat16(v - __bfloat162float(h));
}

// ---------------------------------------------------------------------------
// Elementwise split: fp32 [n] -> hi/lo bf16
// ---------------------------------------------------------------------------
__global__ __launch_bounds__(256) void conv_split_kernel(
    const float* __restrict__ in, __nv_bfloat16* __restrict__ hi,
    __nv_bfloat16* __restrict__ lo, int n)
{
    int i = (blockIdx.x * 256 + threadIdx.x) * 4;
    if (i >= n) return;
    float4 v = *(const float4*)(in + i);
    __nv_bfloat16 h[4], l[4];
    split_bf16(v.x, h[0], l[0]);
    split_bf16(v.y, h[1], l[1]);
    split_bf16(v.z, h[2], l[2]);
    split_bf16(v.w, h[3], l[3]);
    *(__nv_bfloat162*)(hi + i)     = __nv_bfloat162(h[0], h[1]);
    *(__nv_bfloat162*)(hi + i + 2) = __nv_bfloat162(h[2], h[3]);
    *(__nv_bfloat162*)(lo + i)     = __nv_bfloat162(l[0], l[1]);
    *(__nv_bfloat162*)(lo + i + 2) = __nv_bfloat162(l[2], l[3]);
}

// ---------------------------------------------------------------------------
// Transpose + split: W [K,N] fp32 -> Wt hi/lo bf16 [N,K]
// ---------------------------------------------------------------------------
__global__ __launch_bounds__(256) void conv_wt_kernel(
    const float* __restrict__ W, __nv_bfloat16* __restrict__ Thi,
    __nv_bfloat16* __restrict__ Tlo, int K, int N)
{
    __shared__ float t[32][33];
    const int bx = blockIdx.x * 32;   // N offset
    const int by = blockIdx.y * 32;   // K offset
    const int tx = threadIdx.x & 31;
    const int ty = threadIdx.x >> 5;  // 0..7
    #pragma unroll
    for (int i = 0; i < 4; ++i)
        t[ty + i * 8][tx] = W[(long)(by + ty + i * 8) * N + bx + tx];
    __syncthreads();
    #pragma unroll
    for (int i = 0; i < 4; ++i) {
        int n = bx + ty + i * 8;
        int k = by + tx;
        float v = t[tx][ty + i * 8];
        __nv_bfloat16 h, l;
        split_bf16(v, h, l);
        Thi[(long)n * K + k] = h;
        Tlo[(long)n * K + k] = l;
    }
}

// ---------------------------------------------------------------------------
// GEMM (unchanged from R9): split-bf16 3-MMA, ldmatrix, cp.async.
// ---------------------------------------------------------------------------
#define AHI_OFF 0
#define ALO_OFF 16384
#define BHI_OFF 32768
#define BLO_OFF 40960
#define STG_SZ  49152

__global__ __launch_bounds__(256, 2) void gemm_mma_kernel(
    const __nv_bfloat16* __restrict__ Ahi, const __nv_bfloat16* __restrict__ Alo,
    const __nv_bfloat16* __restrict__ Bhi, const __nv_bfloat16* __restrict__ Blo,
    const float* __restrict__ bias, float* __restrict__ C,
    int M, int N, int K)
{
    extern __shared__ char smem[];
    const uint32_t sbase = smem_u32(smem);

    const int tid  = threadIdx.x;
    const int lane = tid & 31;
    const int wid  = tid >> 5;
    const int wm   = (wid & 3) * 32;
    const int wn   = (wid >> 2) * 32;

    const long rowA = blockIdx.y * 128 + (tid >> 1);
    const int  ac0  = (tid & 1) * 4;
    const long rowB = blockIdx.x * 64 + (tid >> 2);
    const int  bc0  = (tid & 3) * 2;

    const __nv_bfloat16* pAh = Ahi + rowA * K + ac0 * 8;
    const __nv_bfloat16* pAl = Alo + rowA * K + ac0 * 8;
    const __nv_bfloat16* pBh = Bhi + rowB * K + bc0 * 8;
    const __nv_bfloat16* pBl = Blo + rowB * K + bc0 * 8;

    uint32_t aswz[4], bswz[2];
    #pragma unroll
    for (int j = 0; j < 4; ++j)
        aswz[j] = SWZ((tid >> 1) * 128 + (ac0 + j) * 16);
    #pragma unroll
    for (int j = 0; j < 2; ++j)
        bswz[j] = SWZ((tid >> 2) * 128 + (bc0 + j) * 16);

    auto load_chunk = [&](int ck, int s) {
        const uint32_t base = sbase + s * STG_SZ;
        const long go = (long)ck * 64;
        #pragma unroll
        for (int j = 0; j < 4; ++j) {
            cp_async16(base + AHI_OFF + aswz[j], pAh + go + j * 8);
            cp_async16(base + ALO_OFF + aswz[j], pAl + go + j * 8);
        }
        #pragma unroll
        for (int j = 0; j < 2; ++j) {
            cp_async16(base + BHI_OFF + bswz[j], pBh + go + j * 8);
            cp_async16(base + BLO_OFF + bswz[j], pBl + go + j * 8);
        }
    };

    const int a_row = (lane & 7) + ((lane >> 3) & 1) * 8;
    const int a_kc  = lane >> 4;
    const int b_row = (lane & 7) + ((lane >> 4) & 1) * 8;
    const int b_kc  = (lane >> 3) & 1;

    const int arow0 = (wm + a_row) * 128;
    const int arow1 = (wm + 16 + a_row) * 128;
    const int brow0 = (wn + b_row) * 128;
    const int brow1 = (wn + 16 + b_row) * 128;

    float acc[2][4][4];
    #pragma unroll
    for (int i = 0; i < 2; ++i)
        #pragma unroll
        for (int j = 0; j < 4; ++j)
            #pragma unroll
            for (int k = 0; k < 4; ++k) acc[i][j][k] = 0.0f;

    load_chunk(0, 0);
    CP_COMMIT();

    const int nk = K / 64;
    for (int t = 0; t < nk; ++t) {
        const int s = t & 1;
        const bool has_next = (t + 1 < nk);
        if (has_next) {
            load_chunk(t + 1, s ^ 1);
            CP_COMMIT();
            asm volatile("cp.async.wait_group 1;" ::: "memory");
        } else {
            asm volatile("cp.async.wait_group 0;" ::: "memory");
        }
        __syncthreads();

        const uint32_t sb = sbase + s * STG_SZ;
        #pragma unroll
        for (int ks = 0; ks < 4; ++ks) {
            const int akc = ks * 2 + a_kc;
            const int bkc = ks * 2 + b_kc;
            unsigned ah0[4], ah1[4], al0[4], al1[4];
            unsigned bh0[4], bh1[4], bl0[4], bl1[4];
            ldsm_x4(ah0[0], ah0[1], ah0[2], ah0[3], sb + AHI_OFF + SWZ(arow0 + akc * 16));
            ldsm_x4(ah1[0], ah1[1], ah1[2], ah1[3], sb + AHI_OFF + SWZ(arow1 + akc * 16));
            ldsm_x4(al0[0], al0[1], al0[2], al0[3], sb + ALO_OFF + SWZ(arow0 + akc * 16));
            ldsm_x4(al1[0], al1[1], al1[2], al1[3], sb + ALO_OFF + SWZ(arow1 + akc * 16));
            ldsm_x4(bh0[0], bh0[1], bh0[2], bh0[3], sb + BHI_OFF + SWZ(brow0 + bkc * 16));
            ldsm_x4(bh1[0], bh1[1], bh1[2], bh1[3], sb + BHI_OFF + SWZ(brow1 + bkc * 16));
            ldsm_x4(bl0[0], bl0[1], bl0[2], bl0[3], sb + BLO_OFF + SWZ(brow0 + bkc * 16));
            ldsm_x4(bl1[0], bl1[1], bl1[2], bl1[3], sb + BLO_OFF + SWZ(brow1 + bkc * 16));

            #pragma unroll
            for (int mf = 0; mf < 2; ++mf) {
                unsigned* ah = mf ? ah1 : ah0;
                unsigned* al = mf ? al1 : al0;
                #pragma unroll
                for (int nf2 = 0; nf2 < 2; ++nf2) {
                    unsigned* bh = nf2 ? bh1 : bh0;
                    unsigned* bl = nf2 ? bl1 : bl0;
                    #pragma unroll
                    for (int sub = 0; sub < 2; ++sub) {
                        float* c = acc[mf][nf2 * 2 + sub];
                        mma_bf16(c, ah[0], ah[1], ah[2], ah[3], bh[sub*2], bh[sub*2+1]);
                        mma_bf16(c, ah[0], ah[1], ah[2], ah[3], bl[sub*2], bl[sub*2+1]);
                        mma_bf16(c, al[0], al[1], al[2], al[3], bh[sub*2], bh[sub*2+1]);
                    }
                }
            }
        }
        __syncthreads();
    }

    const int gr = lane >> 2;
    const int gc = (lane & 3) * 2;
    #pragma unroll
    for (int mf = 0; mf < 2; ++mf) {
        #pragma unroll
        for (int nf = 0; nf < 4; ++nf) {
            int col = blockIdx.x * 64 + wn + nf * 8 + gc;
            float2 bi = *(const float2*)(bias + col);
            int row = blockIdx.y * 128 + wm + mf * 16 + gr;
            float* c0 = C + (long)row * N + col;
            float* c1 = C + (long)(row + 8) * N + col;
            *(float2*)c0 = make_float2(acc[mf][nf][0] + bi.x, acc[mf][nf][1] + bi.y);
            *(float2*)c1 = make_float2(acc[mf][nf][2] + bi.x, acc[mf][nf][3] + bi.y);
        }
    }
}

// ---------------------------------------------------------------------------
// Flash attention: tf32 QK, fp32 online softmax, fp16 PV via ldmatrix.
// BM=128 q rows, 256 threads (8 warps x 16 rows). Grid (S/128, H, B).
// Dyn smem 56KB: Q fp32 128x64 (32KB, P fp16 overlays first 16KB after
// frag extraction) | K fp32 [d][c] (16KB) | V fp16 [c][d] (8KB).
// ---------------------------------------------------------------------------
#define ATT_KS_OFF 32768
#define ATT_VS_OFF 49152
#define ATT_SMEM   57344

__global__ __launch_bounds__(256, 2) void attn_tf32_kernel(
    const float* __restrict__ qkv,
    __nv_bfloat16* __restrict__ ohi, __nv_bfloat16* __restrict__ olo)
{
    extern __shared__ char asmem[];
    float* PS = (float*)asmem;                  // Q fp32
    float* Ks = (float*)(asmem + ATT_KS_OFF);   // K fp32 [d][c]
    char*  VB = asmem + ATT_VS_OFF;             // V fp16 bytes [c][d]
    char*  PB = asmem;                          // P fp16 bytes [r][c]
    const uint32_t ps_u = smem_u32(asmem);
    const uint32_t vs_u = ps_u + ATT_VS_OFF;

    const int tid  = threadIdx.x;
    const int lane = tid & 31;
    const int wid  = tid >> 5;
    const int q    = lane >> 2;
    const int sq   = lane & 3;

    const int h    = blockIdx.y;
    const int b    = blockIdx.z;
    const int tok0 = b * Sq + blockIdx.x * 128;

    const float* qbase = qkv + h * HDq;
    const float* kbase = qkv + Dq + h * HDq;
    const float* vbase = qkv + 2 * Dq + h * HDq;

    // ---- load Q tile 128x64 (scaled, tf32) swizzled ----
    #pragma unroll
    for (int it = 0; it < 8; ++it) {
        int idx = tid + it * 256;            // 0..2047
        int r   = idx >> 4;                  // 0..127
        int d0  = (idx & 15) * 4;
        float4 v = *(const float4*)(qbase + (long)(tok0 + r) * QKVN + d0);
        int base = r * 64 + (d0 ^ ((r & 7) << 3));
        PS[base + 0] = tf32r(v.x * 0.125f);
        PS[base + 1] = tf32r(v.y * 0.125f);
        PS[base + 2] = tf32r(v.z * 0.125f);
        PS[base + 3] = tf32r(v.w * 0.125f);
    }
    __syncthreads();

    const int rl  = wid * 16 + q;            // thread's low row
    const int rl0 = wid * 16;                // warp row base

    // ---- extract Q fragments (own warp rows) ----
    unsigned qf[8][4];
    #pragma unroll
    for (int kk = 0; kk < 8; ++kk) {
        int base = rl * 64 + ((kk ^ q) << 3) + sq;
        qf[kk][0] = fbits(PS[base]);
        qf[kk][1] = fbits(PS[base + 512]);
        qf[kk][2] = fbits(PS[base + 4]);
        qf[kk][3] = fbits(PS[base + 516]);
    }

    float O[8][4];
    #pragma unroll
    for (int nf = 0; nf < 8; ++nf)
        #pragma unroll
        for (int k = 0; k < 4; ++k) O[nf][k] = 0.0f;
    float m0 = -1e30f, m1 = -1e30f, l0 = 0.0f, l1 = 0.0f;

    for (int kt = 0; kt < Sq / 64; ++kt) {
        const int ktok0 = b * Sq + kt * 64;
        __syncthreads();   // previous tile K/V reads + P reads complete
        // ---- stage K (fp32 tf32, [d][c] swizzled) and V (fp16, [c][d]) ----
        #pragma unroll
        for (int it = 0; it < 4; ++it) {
            int idx = tid + it * 256;        // 0..1023
            int c   = idx >> 4;              // 0..63
            int d0  = (idx & 15) * 4;
            float4 kv = *(const float4*)(kbase + (long)(ktok0 + c) * QKVN + d0);
            Ks[(d0 + 0) * 64 + (c ^ (((d0 + 0) & 7) << 3))] = tf32r(kv.x);
            Ks[(d0 + 1) * 64 + (c ^ (((d0 + 1) & 7) << 3))] = tf32r(kv.y);
            Ks[(d0 + 2) * 64 + (c ^ (((d0 + 2) & 7) << 3))] = tf32r(kv.z);
            Ks[(d0 + 3) * 64 + (c ^ (((d0 + 3) & 7) << 3))] = tf32r(kv.w);
            float4 vv = *(const float4*)(vbase + (long)(ktok0 + c) * QKVN + d0);
            uint32_t vbyte = (uint32_t)(c * 128 + d0 * 2);
            *(__half2*)(VB + SWZ(vbyte))     = __floats2half2_rn(vv.x, vv.y);
            *(__half2*)(VB + SWZ(vbyte) + 4) = __floats2half2_rn(vv.z, vv.w);
        }
        __syncthreads();

        // ---- scores: sc = Q @ K^T (tf32) ----
        float sc[8][4];
        #pragma unroll
        for (int nf = 0; nf < 8; ++nf) {
            sc[nf][0] = sc[nf][1] = sc[nf][2] = sc[nf][3] = 0.0f;
            int cx = ((nf ^ sq) << 3) + q;
            const float* p0 = Ks + sq * 64 + cx;
            const float* p1 = Ks + (sq + 4) * 64 + (cx ^ 32);
            #pragma unroll
            for (int kk = 0; kk < 8; ++kk) {
                unsigned b0 = fbits(p0[kk * 512]);
                unsigned b1 = fbits(p1[kk * 512]);
                mma_tf32(sc[nf], qf[kk][0], qf[kk][1], qf[kk][2], qf[kk][3], b0, b1);
            }
        }

        // ---- online softmax (fp32 exp) ----
        float mx0 = -1e30f, mx1 = -1e30f;
        #pragma unroll
        for (int nf = 0; nf < 8; ++nf) {
            mx0 = fmaxf(mx0, fmaxf(sc[nf][0], sc[nf][1]));
            mx1 = fmaxf(mx1, fmaxf(sc[nf][2], sc[nf][3]));
        }
        mx0 = fmaxf(mx0, __shfl_xor_sync(0xffffffffu, mx0, 1));
        mx0 = fmaxf(mx0, __shfl_xor_sync(0xffffffffu, mx0, 2));
        mx1 = fmaxf(mx1, __shfl_xor_sync(0xffffffffu, mx1, 1));
        mx1 = fmaxf(mx1, __shfl_xor_sync(0xffffffffu, mx1, 2));
        float mn0 = fmaxf(m0, mx0), mn1 = fmaxf(m1, mx1);
        float al0 = __expf(m0 - mn0), al1 = __expf(m1 - mn1);
        float s0 = 0.0f, s1 = 0.0f;
        #pragma unroll
        for (int nf = 0; nf < 8; ++nf) {
            sc[nf][0] = __expf(sc[nf][0] - mn0);
            sc[nf][1] = __expf(sc[nf][1] - mn0);
            sc[nf][2] = __expf(sc[nf][2] - mn1);
            sc[nf][3] = __expf(sc[nf][3] - mn1);
            s0 += sc[nf][0] + sc[nf][1];
            s1 += sc[nf][2] + sc[nf][3];
        }
        s0 += __shfl_xor_sync(0xffffffffu, s0, 1);
        s0 += __shfl_xor_sync(0xffffffffu, s0, 2);
        s1 += __shfl_xor_sync(0xffffffffu, s1, 1);
        s1 += __shfl_xor_sync(0xffffffffu, s1, 2);
        l0 = l0 * al0 + s0;  m0 = mn0;
        l1 = l1 * al1 + s1;  m1 = mn1;
        #pragma unroll
        for (int nf = 0; nf < 8; ++nf) {
            O[nf][0] *= al0; O[nf][1] *= al0;
            O[nf][2] *= al1; O[nf][3] *= al1;
        }

        // ---- store P as fp16 (own warp rows) ----
        #pragma unroll
        for (int nf = 0; nf < 8; ++nf) {
            unsigned pp0 = pack_f16x2(sc[nf][1], sc[nf][0]);
            unsigned pp1 = pack_f16x2(sc[nf][3], sc[nf][2]);
            *(unsigned*)(PB + SWZ(rl * 128 + nf * 16 + 4 * sq))       = pp0;
            *(unsigned*)(PB + SWZ((rl + 8) * 128 + nf * 16 + 4 * sq)) = pp1;
        }
        __syncwarp();

        // ---- O += P @ V  (fp16 m16n8k16, ldmatrix frags) ----
        #pragma unroll
        for (int kf = 0; kf < 4; ++kf) {
            unsigned pa0, pa1, pa2, pa3;
            uint32_t paddr = ps_u +
                SWZ((rl0 + (lane & 15)) * 128 + kf * 32 + ((lane >> 4) & 1) * 16);
            ldsm_x4(pa0, pa1, pa2, pa3, paddr);
            #pragma unroll
            for (int nfp = 0; nfp < 4; ++nfp) {
                unsigned vb0, vb1, vb2, vb3;
                uint32_t vaddr = vs_u +
                    SWZ((kf * 16 + (lane & 15)) * 128 + nfp * 32 + ((lane >> 4) & 1) * 16);
                ldsm_x4_t(vb0, vb1, vb2, vb3, vaddr);
                mma_f16(O[nfp * 2],     pa0, pa1, pa2, pa3, vb0, vb1);
                mma_f16(O[nfp * 2 + 1], pa0, pa1, pa2, pa3, vb2, vb3);
            }
        }
    }

    // ---- epilogue: normalize, write hi/lo bf16 split ----
    float inv0 = 1.0f / l0, inv1 = 1.0f / l1;
    #pragma unroll
    for (int nf = 0; nf < 8; ++nf) {
        int c = h * HDq + nf * 8 + 2 * sq;
        long i0 = (long)(tok0 + rl) * Dq + c;
        long i1 = (long)(tok0 + rl + 8) * Dq + c;
        __nv_bfloat16 h0, l0b, h1, l1b;
        split_bf16(O[nf][0] * inv0, h0, l0b);
        split_bf16(O[nf][1] * inv0, h1, l1b);
        *(__nv_bfloat162*)(ohi + i0) = __nv_bfloat162(h0, h1);
        *(__nv_bfloat162*)(olo + i0) = __nv_bfloat162(l0b, l1b);
        split_bf16(O[nf][2] * inv1, h0, l0b);
        split_bf16(O[nf][3] * inv1, h1, l1b);
        *(__nv_bfloat162*)(ohi + i1) = __nv_bfloat162(h0, h1);
        *(__nv_bfloat162*)(olo + i1) = __nv_bfloat162(l0b, l1b);
    }
}

// ---------------------------------------------------------------------------
// Launch
// ---------------------------------------------------------------------------
extern "C" void kernel_launch(void* const* d_in, const int* in_sizes, int n_in,
                              void* d_out, int out_size)
{
    const float* x      = (const float*)d_in[0];
    const float* W_qkv  = (const float*)d_in[1];
    const float* b_qkv  = (const float*)d_in[2];
    const float* W_proj = (const float*)d_in[3];
    const float* b_proj = (const float*)d_in[4];
    float* outp = (float*)d_out;

    float *qkv;
    __nv_bfloat16 *xhi, *xlo, *wqh, *wql, *wph, *wpl, *ahi, *alo;
    cudaGetSymbolAddress((void**)&qkv, g_qkv);
    cudaGetSymbolAddress((void**)&xhi, g_xhi);
    cudaGetSymbolAddress((void**)&xlo, g_xlo);
    cudaGetSymbolAddress((void**)&wqh, g_wqkvt_hi);
    cudaGetSymbolAddress((void**)&wql, g_wqkvt_lo);
    cudaGetSymbolAddress((void**)&wph, g_wprot_hi);
    cudaGetSymbolAddress((void**)&wpl, g_wprot_lo);
    cudaGetSymbolAddress((void**)&ahi, g_ahi);
    cudaGetSymbolAddress((void**)&alo, g_alo);

    cudaFuncSetAttribute(gemm_mma_kernel,
                         cudaFuncAttributeMaxDynamicSharedMemorySize, 2 * STG_SZ);
    cudaFuncSetAttribute(attn_tf32_kernel,
                         cudaFuncAttributeMaxDynamicSharedMemorySize, ATT_SMEM);

    // 0) precision splits
    conv_split_kernel<<<(NTOK * Dq) / 1024, 256>>>(x, xhi, xlo, NTOK * Dq);
    {
        dim3 grid(QKVN / 32, Dq / 32);
        conv_wt_kernel<<<grid, 256>>>(W_qkv, wqh, wql, Dq, QKVN);
    }
    {
        dim3 grid(Dq / 32, Dq / 32);
        conv_wt_kernel<<<grid, 256>>>(W_proj, wph, wpl, Dq, Dq);
    }

    // 1) QKV projection: [4096,1024] @ [1024,3072] + b
    {
        dim3 grid(QKVN / 64, NTOK / 128);
        gemm_mma_kernel<<<grid, 256, 2 * STG_SZ>>>(xhi, xlo, wqh, wql, b_qkv, qkv,
                                                   NTOK, QKVN, Dq);
    }
    // 2) Attention (tf32 QK / fp16 PV), writes hi/lo split
    {
        dim3 grid(Sq / 128, Hq, Bq);
        attn_tf32_kernel<<<grid, 256, ATT_SMEM>>>(qkv, ahi, alo);
    }
    // 3) Output projection: [4096,1024] @ [1024,1024] + b
    {
        dim3 grid(Dq / 64, NTOK / 128);
        gemm_mma_kernel<<<grid, 256, 2 * STG_SZ>>>(ahi, alo, wph, wpl, b_proj, outp,
                                                   NTOK, Dq, Dq);
    }
}

// round 15
// speedup vs baseline: 3.0916x; 1.1571x over previous
#include <cuda_runtime.h>
#include <cuda_bf16.h>
#include <cuda_fp16.h>
#include <cstdint>

// Problem constants
#define Bq   2
#define Sq   2048
#define Dq   1024
#define Hq   16
#define HDq  64
#define NTOK (Bq * Sq)          // 4096
#define QKVN (3 * Dq)           // 3072

// Scratch (device globals: allocation-free rule)
__device__ float g_qkv[NTOK * QKVN];                 // fp32 Q|K (pre-formatted); V slot unused
__device__ __half g_vh[NTOK * Dq];                   // V fp16 [b,h,s,d]
__device__ __nv_bfloat16 g_xhi[NTOK * Dq];           // x split
__device__ __nv_bfloat16 g_xlo[NTOK * Dq];
__device__ __nv_bfloat16 g_wqkvt_hi[QKVN * Dq];      // W_qkv^T [N,K]
__device__ __nv_bfloat16 g_wqkvt_lo[QKVN * Dq];
__device__ __nv_bfloat16 g_wprot_hi[Dq * Dq];        // W_proj^T [N,K]
__device__ __nv_bfloat16 g_wprot_lo[Dq * Dq];
__device__ __nv_bfloat16 g_ahi[NTOK * Dq];           // attention out split
__device__ __nv_bfloat16 g_alo[NTOK * Dq];

// ---------------------------------------------------------------------------
// Helpers
// ---------------------------------------------------------------------------
__device__ __forceinline__ uint32_t smem_u32(const void* p)
{
    uint32_t a;
    asm("{ .reg .u64 t; cvta.to.shared.u64 t, %1; cvt.u32.u64 %0, t; }"
        : "=r"(a) : "l"(p));
    return a;
}

#define SWZ(x) ((x) ^ (((x) >> 3) & 0x70))

__device__ __forceinline__ void cp_async16(uint32_t dst, const void* src)
{
    asm volatile("cp.async.cg.shared.global [%0], [%1], 16;" :: "r"(dst), "l"(src));
}
#define CP_COMMIT() asm volatile("cp.async.commit_group;" ::: "memory")

__device__ __forceinline__ void ldsm_x4(unsigned& r0, unsigned& r1,
                                        unsigned& r2, unsigned& r3, uint32_t a)
{
    asm volatile("ldmatrix.sync.aligned.m8n8.x4.shared.b16 {%0,%1,%2,%3}, [%4];"
                 : "=r"(r0), "=r"(r1), "=r"(r2), "=r"(r3) : "r"(a));
}

__device__ __forceinline__ void ldsm_x4_t(unsigned& r0, unsigned& r1,
                                          unsigned& r2, unsigned& r3, uint32_t a)
{
    asm volatile("ldmatrix.sync.aligned.m8n8.x4.trans.shared.b16 {%0,%1,%2,%3}, [%4];"
                 : "=r"(r0), "=r"(r1), "=r"(r2), "=r"(r3) : "r"(a));
}

__device__ __forceinline__ void mma_bf16(float* c, unsigned a0, unsigned a1,
                                         unsigned a2, unsigned a3,
                                         unsigned b0, unsigned b1)
{
    asm volatile(
        "mma.sync.aligned.m16n8k16.row.col.f32.bf16.bf16.f32 "
        "{%0,%1,%2,%3}, {%4,%5,%6,%7}, {%8,%9}, {%0,%1,%2,%3};\n"
        : "+f"(c[0]), "+f"(c[1]), "+f"(c[2]), "+f"(c[3])
        : "r"(a0), "r"(a1), "r"(a2), "r"(a3), "r"(b0), "r"(b1));
}

__device__ __forceinline__ void mma_f16(float* c, unsigned a0, unsigned a1,
                                        unsigned a2, unsigned a3,
                                        unsigned b0, unsigned b1)
{
    asm volatile(
        "mma.sync.aligned.m16n8k16.row.col.f32.f16.f16.f32 "
        "{%0,%1,%2,%3}, {%4,%5,%6,%7}, {%8,%9}, {%0,%1,%2,%3};\n"
        : "+f"(c[0]), "+f"(c[1]), "+f"(c[2]), "+f"(c[3])
        : "r"(a0), "r"(a1), "r"(a2), "r"(a3), "r"(b0), "r"(b1));
}

__device__ __forceinline__ void mma_tf32(float* c, unsigned a0, unsigned a1,
                                         unsigned a2, unsigned a3,
                                         unsigned b0, unsigned b1)
{
    asm volatile(
        "mma.sync.aligned.m16n8k8.row.col.f32.tf32.tf32.f32 "
        "{%0,%1,%2,%3}, {%4,%5,%6,%7}, {%8,%9}, {%0,%1,%2,%3};\n"
        : "+f"(c[0]), "+f"(c[1]), "+f"(c[2]), "+f"(c[3])
        : "r"(a0), "r"(a1), "r"(a2), "r"(a3), "r"(b0), "r"(b1));
}
__device__ __forceinline__ float tf32r(float x)
{
    float y;
    asm("cvt.rna.tf32.f32 %0, %1;" : "=f"(y) : "f"(x));
    return y;
}
__device__ __forceinline__ unsigned fbits(float x) { return __float_as_uint(x); }

__device__ __forceinline__ unsigned pack_f16x2(float hi, float lo)
{
    unsigned d;
    asm("cvt.rn.f16x2.f32 %0, %1, %2;" : "=r"(d) : "f"(hi), "f"(lo));
    return d;
}

__device__ __forceinline__ void split_bf16(float v, __nv_bfloat16& h, __nv_bfloat16& l)
{
    h = __float2bfloat16(v);
    l = __float2bfloat16(v - __bfloat162float(h));
}

// ---------------------------------------------------------------------------
// Elementwise split: fp32 [n] -> hi/lo bf16
// ---------------------------------------------------------------------------
__global__ __launch_bounds__(256) void conv_split_kernel(
    const float* __restrict__ in, __nv_bfloat16* __restrict__ hi,
    __nv_bfloat16* __restrict__ lo, int n)
{
    int i = (blockIdx.x * 256 + threadIdx.x) * 4;
    if (i >= n) return;
    float4 v = *(const float4*)(in + i);
    __nv_bfloat16 h[4], l[4];
    split_bf16(v.x, h[0], l[0]);
    split_bf16(v.y, h[1], l[1]);
    split_bf16(v.z, h[2], l[2]);
    split_bf16(v.w, h[3], l[3]);
    *(__nv_bfloat162*)(hi + i)     = __nv_bfloat162(h[0], h[1]);
    *(__nv_bfloat162*)(hi + i + 2) = __nv_bfloat162(h[2], h[3]);
    *(__nv_bfloat162*)(lo + i)     = __nv_bfloat162(l[0], l[1]);
    *(__nv_bfloat162*)(lo + i + 2) = __nv_bfloat162(l[2], l[3]);
}

// ---------------------------------------------------------------------------
// Transpose + split: W [K,N] fp32 -> Wt hi/lo bf16 [N,K]
// ---------------------------------------------------------------------------
__global__ __launch_bounds__(256) void conv_wt_kernel(
    const float* __restrict__ W, __nv_bfloat16* __restrict__ Thi,
    __nv_bfloat16* __restrict__ Tlo, int K, int N)
{
    __shared__ float t[32][33];
    const int bx = blockIdx.x * 32;   // N offset
    const int by = blockIdx.y * 32;   // K offset
    const int tx = threadIdx.x & 31;
    const int ty = threadIdx.x >> 5;  // 0..7
    #pragma unroll
    for (int i = 0; i < 4; ++i)
        t[ty + i * 8][tx] = W[(long)(by + ty + i * 8) * N + bx + tx];
    __syncthreads();
    #pragma unroll
    for (int i = 0; i < 4; ++i) {
        int n = bx + ty + i * 8;
        int k = by + tx;
        float v = t[tx][ty + i * 8];
        __nv_bfloat16 h, l;
        split_bf16(v, h, l);
        Thi[(long)n * K + k] = h;
        Tlo[(long)n * K + k] = l;
    }
}

// ---------------------------------------------------------------------------
// GEMM: split-bf16 3-MMA, ldmatrix, cp.async (R9 core).
// mode 0: plain C = A@B^T + bias (fp32).
// mode 1 (QKV): Q cols -> tf32r(v*0.125); K cols -> tf32r(v);
//               V cols -> fp16 into g_vh[b,h,s,d] (no fp32 write).
// ---------------------------------------------------------------------------
#define AHI_OFF 0
#define ALO_OFF 16384
#define BHI_OFF 32768
#define BLO_OFF 40960
#define STG_SZ  49152

__global__ __launch_bounds__(256, 2) void gemm_mma_kernel(
    const __nv_bfloat16* __restrict__ Ahi, const __nv_bfloat16* __restrict__ Alo,
    const __nv_bfloat16* __restrict__ Bhi, const __nv_bfloat16* __restrict__ Blo,
    const float* __restrict__ bias, float* __restrict__ C,
    int M, int N, int K, int mode)
{
    extern __shared__ char smem[];
    const uint32_t sbase = smem_u32(smem);

    const int tid  = threadIdx.x;
    const int lane = tid & 31;
    const int wid  = tid >> 5;
    const int wm   = (wid & 3) * 32;
    const int wn   = (wid >> 2) * 32;

    const long rowA = blockIdx.y * 128 + (tid >> 1);
    const int  ac0  = (tid & 1) * 4;
    const long rowB = blockIdx.x * 64 + (tid >> 2);
    const int  bc0  = (tid & 3) * 2;

    const __nv_bfloat16* pAh = Ahi + rowA * K + ac0 * 8;
    const __nv_bfloat16* pAl = Alo + rowA * K + ac0 * 8;
    const __nv_bfloat16* pBh = Bhi + rowB * K + bc0 * 8;
    const __nv_bfloat16* pBl = Blo + rowB * K + bc0 * 8;

    uint32_t aswz[4], bswz[2];
    #pragma unroll
    for (int j = 0; j < 4; ++j)
        aswz[j] = SWZ((tid >> 1) * 128 + (ac0 + j) * 16);
    #pragma unroll
    for (int j = 0; j < 2; ++j)
        bswz[j] = SWZ((tid >> 2) * 128 + (bc0 + j) * 16);

    auto load_chunk = [&](int ck, int s) {
        const uint32_t base = sbase + s * STG_SZ;
        const long go = (long)ck * 64;
        #pragma unroll
        for (int j = 0; j < 4; ++j) {
            cp_async16(base + AHI_OFF + aswz[j], pAh + go + j * 8);
            cp_async16(base + ALO_OFF + aswz[j], pAl + go + j * 8);
        }
        #pragma unroll
        for (int j = 0; j < 2; ++j) {
            cp_async16(base + BHI_OFF + bswz[j], pBh + go + j * 8);
            cp_async16(base + BLO_OFF + bswz[j], pBl + go + j * 8);
        }
    };

    const int a_row = (lane & 7) + ((lane >> 3) & 1) * 8;
    const int a_kc  = lane >> 4;
    const int b_row = (lane & 7) + ((lane >> 4) & 1) * 8;
    const int b_kc  = (lane >> 3) & 1;

    const int arow0 = (wm + a_row) * 128;
    const int arow1 = (wm + 16 + a_row) * 128;
    const int brow0 = (wn + b_row) * 128;
    const int brow1 = (wn + 16 + b_row) * 128;

    float acc[2][4][4];
    #pragma unroll
    for (int i = 0; i < 2; ++i)
        #pragma unroll
        for (int j = 0; j < 4; ++j)
            #pragma unroll
            for (int k = 0; k < 4; ++k) acc[i][j][k] = 0.0f;

    load_chunk(0, 0);
    CP_COMMIT();

    const int nk = K / 64;
    for (int t = 0; t < nk; ++t) {
        const int s = t & 1;
        const bool has_next = (t + 1 < nk);
        if (has_next) {
            load_chunk(t + 1, s ^ 1);
            CP_COMMIT();
            asm volatile("cp.async.wait_group 1;" ::: "memory");
        } else {
            asm volatile("cp.async.wait_group 0;" ::: "memory");
        }
        __syncthreads();

        const uint32_t sb = sbase + s * STG_SZ;
        #pragma unroll
        for (int ks = 0; ks < 4; ++ks) {
            const int akc = ks * 2 + a_kc;
            const int bkc = ks * 2 + b_kc;
            unsigned ah0[4], ah1[4], al0[4], al1[4];
            unsigned bh0[4], bh1[4], bl0[4], bl1[4];
            ldsm_x4(ah0[0], ah0[1], ah0[2], ah0[3], sb + AHI_OFF + SWZ(arow0 + akc * 16));
            ldsm_x4(ah1[0], ah1[1], ah1[2], ah1[3], sb + AHI_OFF + SWZ(arow1 + akc * 16));
            ldsm_x4(al0[0], al0[1], al0[2], al0[3], sb + ALO_OFF + SWZ(arow0 + akc * 16));
            ldsm_x4(al1[0], al1[1], al1[2], al1[3], sb + ALO_OFF + SWZ(arow1 + akc * 16));
            ldsm_x4(bh0[0], bh0[1], bh0[2], bh0[3], sb + BHI_OFF + SWZ(brow0 + bkc * 16));
            ldsm_x4(bh1[0], bh1[1], bh1[2], bh1[3], sb + BHI_OFF + SWZ(brow1 + bkc * 16));
            ldsm_x4(bl0[0], bl0[1], bl0[2], bl0[3], sb + BLO_OFF + SWZ(brow0 + bkc * 16));
            ldsm_x4(bl1[0], bl1[1], bl1[2], bl1[3], sb + BLO_OFF + SWZ(brow1 + bkc * 16));

            #pragma unroll
            for (int mf = 0; mf < 2; ++mf) {
                unsigned* ah = mf ? ah1 : ah0;
                unsigned* al = mf ? al1 : al0;
                #pragma unroll
                for (int nf2 = 0; nf2 < 2; ++nf2) {
                    unsigned* bh = nf2 ? bh1 : bh0;
                    unsigned* bl = nf2 ? bl1 : bl0;
                    #pragma unroll
                    for (int sub = 0; sub < 2; ++sub) {
                        float* c = acc[mf][nf2 * 2 + sub];
                        mma_bf16(c, ah[0], ah[1], ah[2], ah[3], bh[sub*2], bh[sub*2+1]);
                        mma_bf16(c, ah[0], ah[1], ah[2], ah[3], bl[sub*2], bl[sub*2+1]);
                        mma_bf16(c, al[0], al[1], al[2], al[3], bh[sub*2], bh[sub*2+1]);
                    }
                }
            }
        }
        __syncthreads();
    }

    // ---- epilogue ----
    const int gr = lane >> 2;
    const int gc = (lane & 3) * 2;
    // region: 0 = Q (or mode 0), 1 = K, 2 = V — whole block is one region
    const int region = (mode == 1) ? ((blockIdx.x * 64) >> 10) : 0;
    const float qscale = (mode == 1 && region == 0) ? 0.125f : 1.0f;

    #pragma unroll
    for (int mf = 0; mf < 2; ++mf) {
        #pragma unroll
        for (int nf = 0; nf < 4; ++nf) {
            int col = blockIdx.x * 64 + wn + nf * 8 + gc;
            float2 bi = *(const float2*)(bias + col);
            int row = blockIdx.y * 128 + wm + mf * 16 + gr;
            float v0 = acc[mf][nf][0] + bi.x, v1 = acc[mf][nf][1] + bi.y;
            float v2 = acc[mf][nf][2] + bi.x, v3 = acc[mf][nf][3] + bi.y;
            if (region == 2) {
                // V: fp16 to g_vh[b,h,s,d]
                int d  = col & 63;
                int hh = (col >> 6) & 15;
                int bb = row >> 11, s0 = row & 2047;
                long base = (((long)bb * Hq + hh) * Sq) * HDq + d;
                *(__half2*)&g_vh[base + (long)s0 * HDq] =
                    __floats2half2_rn(v0, v1);
                *(__half2*)&g_vh[base + (long)(s0 + 8) * HDq] =
                    __floats2half2_rn(v2, v3);
            } else {
                if (mode == 1) {
                    v0 = tf32r(v0 * qscale); v1 = tf32r(v1 * qscale);
                    v2 = tf32r(v2 * qscale); v3 = tf32r(v3 * qscale);
                }
                *(float2*)(C + (long)row * N + col)       = make_float2(v0, v1);
                *(float2*)(C + (long)(row + 8) * N + col) = make_float2(v2, v3);
            }
        }
    }
}

// ---------------------------------------------------------------------------
// Flash attention: tf32 QK (conflict-free K layout), fp32 softmax,
// fp16 PV via ldmatrix with double-buffered cp.async V.
// BM=128, 256 threads. K smem layout: elem (d,c) at d*64 + (c ^ hK(d)),
// hK(d) = ((d&3)<<3) ^ (((d>>2)&15)<<1) — conflict-free stores AND reads.
// Dyn smem 64KB: Q/P 32KB | K 16KB | V 2x8KB.
// ---------------------------------------------------------------------------
#define ATT_KS_OFF 32768
#define ATT_VS_OFF 49152
#define ATT_SMEM   65536
#define NKT (Sq / 64)

__global__ __launch_bounds__(256, 2) void attn_tf32_kernel(
    const float* __restrict__ qkv, const __half* __restrict__ vh,
    __nv_bfloat16* __restrict__ ohi, __nv_bfloat16* __restrict__ olo)
{
    extern __shared__ char asmem[];
    float* PS = (float*)asmem;                  // Q fp32 / P fp16 overlay
    float* Ks = (float*)(asmem + ATT_KS_OFF);   // K fp32, custom swizzle
    char*  PB = asmem;
    const uint32_t ps_u = smem_u32(asmem);
    const uint32_t vs_u = ps_u + ATT_VS_OFF;

    const int tid  = threadIdx.x;
    const int lane = tid & 31;
    const int wid  = tid >> 5;
    const int q    = lane >> 2;
    const int sq   = lane & 3;

    const int h    = blockIdx.y;
    const int b    = blockIdx.z;
    const int tok0 = b * Sq + blockIdx.x * 128;

    const float* qbase = qkv + h * HDq;
    const float* kbase = qkv + Dq + h * HDq;
    const char*  vbase = (const char*)(vh + ((long)(b * Hq + h) * Sq) * HDq);

    // ---- prologue: V[0] cp.async into stage 0 ----
    {
        uint32_t byte0 = (uint32_t)tid * 32;
        cp_async16(vs_u + SWZ(byte0),      vbase + byte0);
        cp_async16(vs_u + SWZ(byte0 + 16), vbase + byte0 + 16);
        CP_COMMIT();
    }

    // ---- load Q tile (pre-scaled, pre-rounded by GEMM) ----
    #pragma unroll
    for (int it = 0; it < 8; ++it) {
        int idx = tid + it * 256;
        int r   = idx >> 4;
        int d0  = (idx & 15) * 4;
        float4 v = *(const float4*)(qbase + (long)(tok0 + r) * QKVN + d0);
        *(float4*)&PS[r * 64 + (d0 ^ ((r & 7) << 3))] = v;
    }
    __syncthreads();

    const int rl  = wid * 16 + q;
    const int rl0 = wid * 16;

    unsigned qf[8][4];
    #pragma unroll
    for (int kk = 0; kk < 8; ++kk) {
        int base = rl * 64 + ((kk ^ q) << 3) + sq;
        qf[kk][0] = fbits(PS[base]);
        qf[kk][1] = fbits(PS[base + 512]);
        qf[kk][2] = fbits(PS[base + 4]);
        qf[kk][3] = fbits(PS[base + 516]);
    }

    float O[8][4];
    #pragma unroll
    for (int nf = 0; nf < 8; ++nf)
        #pragma unroll
        for (int k = 0; k < 4; ++k) O[nf][k] = 0.0f;
    float m0 = -1e30f, m1 = -1e30f, l0 = 0.0f, l1 = 0.0f;

    // K staging constants (per thread)
    const int kc_m  = tid & 15;          // d-group (d0 = 4*m)
    const int kc_d0 = kc_m * 4;
    const int kc_sw = kc_m << 1;         // ((d>>2)&15)<<1 part of hK

    for (int kt = 0; kt < NKT; ++kt) {
        const int st = kt & 1;
        __syncthreads();   // all warps done reading K[kt-1] and V[kt-1]

        if (kt + 1 < NKT) {
            // prefetch V[kt+1] into the other stage
            uint32_t byte0 = (uint32_t)tid * 32;
            const char* src = vbase + (long)(kt + 1) * 8192 + byte0;
            uint32_t dst = vs_u + (st ^ 1) * 8192;
            cp_async16(dst + SWZ(byte0),      src);
            cp_async16(dst + SWZ(byte0 + 16), src + 16);
            CP_COMMIT();
        }

        // ---- stage K[kt] (pre-rounded fp32; conflict-free swizzle) ----
        {
            const int ktok0 = b * Sq + kt * 64;
            #pragma unroll
            for (int it = 0; it < 4; ++it) {
                int c = (tid >> 4) + it * 16;
                float4 kv = *(const float4*)(kbase + (long)(ktok0 + c) * QKVN + kc_d0);
                Ks[(kc_d0 + 0) * 64 + (c ^ (0  ^ kc_sw))] = kv.x;
                Ks[(kc_d0 + 1) * 64 + (c ^ (8  ^ kc_sw))] = kv.y;
                Ks[(kc_d0 + 2) * 64 + (c ^ (16 ^ kc_sw))] = kv.z;
                Ks[(kc_d0 + 3) * 64 + (c ^ (24 ^ kc_sw))] = kv.w;
            }
        }

        if (kt + 1 < NKT) {
            asm volatile("cp.async.wait_group 1;" ::: "memory");
        } else {
            asm volatile("cp.async.wait_group 0;" ::: "memory");
        }
        __syncthreads();

        // ---- scores: sc = Q @ K^T (tf32, conflict-free B-frag reads) ----
        float sc[8][4];
        const int sq8 = sq << 3;
        #pragma unroll
        for (int nf = 0; nf < 8; ++nf) {
            sc[nf][0] = sc[nf][1] = sc[nf][2] = sc[nf][3] = 0.0f;
            const int cn = nf * 8 + q;
            #pragma unroll
            for (int kk = 0; kk < 8; ++kk) {
                unsigned b0 = fbits(Ks[(sq + 8 * kk) * 64 +
                                       (cn ^ sq8 ^ (4 * kk))]);
                unsigned b1 = fbits(Ks[(sq + 4 + 8 * kk) * 64 +
                                       (cn ^ sq8 ^ (4 * kk + 2))]);
                mma_tf32(sc[nf], qf[kk][0], qf[kk][1], qf[kk][2], qf[kk][3], b0, b1);
            }
        }

        // ---- online softmax ----
        float mx0 = -1e30f, mx1 = -1e30f;
        #pragma unroll
        for (int nf = 0; nf < 8; ++nf) {
            mx0 = fmaxf(mx0, fmaxf(sc[nf][0], sc[nf][1]));
            mx1 = fmaxf(mx1, fmaxf(sc[nf][2], sc[nf][3]));
        }
        mx0 = fmaxf(mx0, __shfl_xor_sync(0xffffffffu, mx0, 1));
        mx0 = fmaxf(mx0, __shfl_xor_sync(0xffffffffu, mx0, 2));
        mx1 = fmaxf(mx1, __shfl_xor_sync(0xffffffffu, mx1, 1));
        mx1 = fmaxf(mx1, __shfl_xor_sync(0xffffffffu, mx1, 2));
        float mn0 = fmaxf(m0, mx0), mn1 = fmaxf(m1, mx1);
        float al0 = __expf(m0 - mn0), al1 = __expf(m1 - mn1);
        float s0 = 0.0f, s1 = 0.0f;
        #pragma unroll
        for (int nf = 0; nf < 8; ++nf) {
            sc[nf][0] = __expf(sc[nf][0] - mn0);
            sc[nf][1] = __expf(sc[nf][1] - mn0);
            sc[nf][2] = __expf(sc[nf][2] - mn1);
            sc[nf][3] = __expf(sc[nf][3] - mn1);
            s0 += sc[nf][0] + sc[nf][1];
            s1 += sc[nf][2] + sc[nf][3];
        }
        s0 += __shfl_xor_sync(0xffffffffu, s0, 1);
        s0 += __shfl_xor_sync(0xffffffffu, s0, 2);
        s1 += __shfl_xor_sync(0xffffffffu, s1, 1);
        s1 += __shfl_xor_sync(0xffffffffu, s1, 2);
        l0 = l0 * al0 + s0;  m0 = mn0;
        l1 = l1 * al1 + s1;  m1 = mn1;
        #pragma unroll
        for (int nf = 0; nf < 8; ++nf) {
            O[nf][0] *= al0; O[nf][1] *= al0;
            O[nf][2] *= al1; O[nf][3] *= al1;
        }

        // ---- store P as fp16 (own warp rows; overlays Q region) ----
        #pragma unroll
        for (int nf = 0; nf < 8; ++nf) {
            unsigned pp0 = pack_f16x2(sc[nf][1], sc[nf][0]);
            unsigned pp1 = pack_f16x2(sc[nf][3], sc[nf][2]);
            *(unsigned*)(PB + SWZ(rl * 128 + nf * 16 + 4 * sq))       = pp0;
            *(unsigned*)(PB + SWZ((rl + 8) * 128 + nf * 16 + 4 * sq)) = pp1;
        }
        __syncwarp();

        // ---- O += P @ V  (fp16 m16n8k16, ldmatrix frags) ----
        const uint32_t vstage = vs_u + st * 8192;
        #pragma unroll
        for (int kf = 0; kf < 4; ++kf) {
            unsigned pa0, pa1, pa2, pa3;
            uint32_t paddr = ps_u +
                SWZ((rl0 + (lane & 15)) * 128 + kf * 32 + ((lane >> 4) & 1) * 16);
            ldsm_x4(pa0, pa1, pa2, pa3, paddr);
            #pragma unroll
            for (int nfp = 0; nfp < 4; ++nfp) {
                unsigned vb0, vb1, vb2, vb3;
                uint32_t vaddr = vstage +
                    SWZ((kf * 16 + (lane & 15)) * 128 + nfp * 32 + ((lane >> 4) & 1) * 16);
                ldsm_x4_t(vb0, vb1, vb2, vb3, vaddr);
                mma_f16(O[nfp * 2],     pa0, pa1, pa2, pa3, vb0, vb1);
                mma_f16(O[nfp * 2 + 1], pa0, pa1, pa2, pa3, vb2, vb3);
            }
        }
    }

    // ---- epilogue: normalize, write hi/lo bf16 split ----
    float inv0 = 1.0f / l0, inv1 = 1.0f / l1;
    #pragma unroll
    for (int nf = 0; nf < 8; ++nf) {
        int c = h * HDq + nf * 8 + 2 * sq;
        long i0 = (long)(tok0 + rl) * Dq + c;
        long i1 = (long)(tok0 + rl + 8) * Dq + c;
        __nv_bfloat16 h0, l0b, h1, l1b;
        split_bf16(O[nf][0] * inv0, h0, l0b);
        split_bf16(O[nf][1] * inv0, h1, l1b);
        *(__nv_bfloat162*)(ohi + i0) = __nv_bfloat162(h0, h1);
        *(__nv_bfloat162*)(olo + i0) = __nv_bfloat162(l0b, l1b);
        split_bf16(O[nf][2] * inv1, h0, l0b);
        split_bf16(O[nf][3] * inv1, h1, l1b);
        *(__nv_bfloat162*)(ohi + i1) = __nv_bfloat162(h0, h1);
        *(__nv_bfloat162*)(olo + i1) = __nv_bfloat162(l0b, l1b);
    }
}

// ---------------------------------------------------------------------------
// Launch
// ---------------------------------------------------------------------------
extern "C" void kernel_launch(void* const* d_in, const int* in_sizes, int n_in,
                              void* d_out, int out_size)
{
    const float* x      = (const float*)d_in[0];
    const float* W_qkv  = (const float*)d_in[1];
    const float* b_qkv  = (const float*)d_in[2];
    const float* W_proj = (const float*)d_in[3];
    const float* b_proj = (const float*)d_in[4];
    float* outp = (float*)d_out;

    float *qkv;
    __half *vhp;
    __nv_bfloat16 *xhi, *xlo, *wqh, *wql, *wph, *wpl, *ahi, *alo;
    cudaGetSymbolAddress((void**)&qkv, g_qkv);
    cudaGetSymbolAddress((void**)&vhp, g_vh);
    cudaGetSymbolAddress((void**)&xhi, g_xhi);
    cudaGetSymbolAddress((void**)&xlo, g_xlo);
    cudaGetSymbolAddress((void**)&wqh, g_wqkvt_hi);
    cudaGetSymbolAddress((void**)&wql, g_wqkvt_lo);
    cudaGetSymbolAddress((void**)&wph, g_wprot_hi);
    cudaGetSymbolAddress((void**)&wpl, g_wprot_lo);
    cudaGetSymbolAddress((void**)&ahi, g_ahi);
    cudaGetSymbolAddress((void**)&alo, g_alo);

    cudaFuncSetAttribute(gemm_mma_kernel,
                         cudaFuncAttributeMaxDynamicSharedMemorySize, 2 * STG_SZ);
    cudaFuncSetAttribute(attn_tf32_kernel,
                         cudaFuncAttributeMaxDynamicSharedMemorySize, ATT_SMEM);

    // 0) precision splits
    conv_split_kernel<<<(NTOK * Dq) / 1024, 256>>>(x, xhi, xlo, NTOK * Dq);
    {
        dim3 grid(QKVN / 32, Dq / 32);
        conv_wt_kernel<<<grid, 256>>>(W_qkv, wqh, wql, Dq, QKVN);
    }
    {
        dim3 grid(Dq / 32, Dq / 32);
        conv_wt_kernel<<<grid, 256>>>(W_proj, wph, wpl, Dq, Dq);
    }

    // 1) QKV projection (mode 1: writes pre-formatted Q/K fp32 + V fp16)
    {
        dim3 grid(QKVN / 64, NTOK / 128);
        gemm_mma_kernel<<<grid, 256, 2 * STG_SZ>>>(xhi, xlo, wqh, wql, b_qkv, qkv,
                                                   NTOK, QKVN, Dq, 1);
    }
    // 2) Attention, writes hi/lo split
    {
        dim3 grid(Sq / 128, Hq, Bq);
        attn_tf32_kernel<<<grid, 256, ATT_SMEM>>>(qkv, vhp, ahi, alo);
    }
    // 3) Output projection (mode 0)
    {
        dim3 grid(Dq / 64, NTOK / 128);
        gemm_mma_kernel<<<grid, 256, 2 * STG_SZ>>>(ahi, alo, wph, wpl, b_proj, outp,
                                                   NTOK, Dq, Dq, 0);
    }
}

// round 16
// speedup vs baseline: 3.6171x; 1.1700x over previous
#include <cuda_runtime.h>
#include <cuda_bf16.h>
#include <cuda_fp16.h>
#include <cstdint>

// Problem constants
#define Bq   2
#define Sq   2048
#define Dq   1024
#define Hq   16
#define HDq  64
#define NTOK (Bq * Sq)          // 4096
#define QKVN (3 * Dq)           // 3072

// Scratch (device globals: allocation-free rule)
__device__ __half g_qh[NTOK * Dq];                   // Q fp16 [b,h,s,d], pre-scaled
__device__ __half g_kh[NTOK * Dq];                   // K fp16 [b,h,s,d]
__device__ __half g_vh[NTOK * Dq];                   // V fp16 [b,h,s,d]
__device__ __nv_bfloat16 g_xhi[NTOK * Dq];           // x split
__device__ __nv_bfloat16 g_xlo[NTOK * Dq];
__device__ __nv_bfloat16 g_wqkvt_hi[QKVN * Dq];      // W_qkv^T [N,K]
__device__ __nv_bfloat16 g_wqkvt_lo[QKVN * Dq];
__device__ __nv_bfloat16 g_wprot_hi[Dq * Dq];        // W_proj^T [N,K]
__device__ __nv_bfloat16 g_wprot_lo[Dq * Dq];
__device__ __nv_bfloat16 g_ahi[NTOK * Dq];           // attention out split
__device__ __nv_bfloat16 g_alo[NTOK * Dq];

// ---------------------------------------------------------------------------
// Helpers
// ---------------------------------------------------------------------------
__device__ __forceinline__ uint32_t smem_u32(const void* p)
{
    uint32_t a;
    asm("{ .reg .u64 t; cvta.to.shared.u64 t, %1; cvt.u32.u64 %0, t; }"
        : "=r"(a) : "l"(p));
    return a;
}

#define SWZ(x) ((x) ^ (((x) >> 3) & 0x70))

__device__ __forceinline__ void cp_async16(uint32_t dst, const void* src)
{
    asm volatile("cp.async.cg.shared.global [%0], [%1], 16;" :: "r"(dst), "l"(src));
}
#define CP_COMMIT() asm volatile("cp.async.commit_group;" ::: "memory")

__device__ __forceinline__ void ldsm_x4(unsigned& r0, unsigned& r1,
                                        unsigned& r2, unsigned& r3, uint32_t a)
{
    asm volatile("ldmatrix.sync.aligned.m8n8.x4.shared.b16 {%0,%1,%2,%3}, [%4];"
                 : "=r"(r0), "=r"(r1), "=r"(r2), "=r"(r3) : "r"(a));
}

__device__ __forceinline__ void ldsm_x4_t(unsigned& r0, unsigned& r1,
                                          unsigned& r2, unsigned& r3, uint32_t a)
{
    asm volatile("ldmatrix.sync.aligned.m8n8.x4.trans.shared.b16 {%0,%1,%2,%3}, [%4];"
                 : "=r"(r0), "=r"(r1), "=r"(r2), "=r"(r3) : "r"(a));
}

__device__ __forceinline__ void mma_bf16(float* c, unsigned a0, unsigned a1,
                                         unsigned a2, unsigned a3,
                                         unsigned b0, unsigned b1)
{
    asm volatile(
        "mma.sync.aligned.m16n8k16.row.col.f32.bf16.bf16.f32 "
        "{%0,%1,%2,%3}, {%4,%5,%6,%7}, {%8,%9}, {%0,%1,%2,%3};\n"
        : "+f"(c[0]), "+f"(c[1]), "+f"(c[2]), "+f"(c[3])
        : "r"(a0), "r"(a1), "r"(a2), "r"(a3), "r"(b0), "r"(b1));
}

__device__ __forceinline__ void mma_f16(float* c, unsigned a0, unsigned a1,
                                        unsigned a2, unsigned a3,
                                        unsigned b0, unsigned b1)
{
    asm volatile(
        "mma.sync.aligned.m16n8k16.row.col.f32.f16.f16.f32 "
        "{%0,%1,%2,%3}, {%4,%5,%6,%7}, {%8,%9}, {%0,%1,%2,%3};\n"
        : "+f"(c[0]), "+f"(c[1]), "+f"(c[2]), "+f"(c[3])
        : "r"(a0), "r"(a1), "r"(a2), "r"(a3), "r"(b0), "r"(b1));
}

__device__ __forceinline__ unsigned pack_f16x2(float hi, float lo)
{
    unsigned d;
    asm("cvt.rn.f16x2.f32 %0, %1, %2;" : "=r"(d) : "f"(hi), "f"(lo));
    return d;
}

__device__ __forceinline__ void split_bf16(float v, __nv_bfloat16& h, __nv_bfloat16& l)
{
    h = __float2bfloat16(v);
    l = __float2bfloat16(v - __bfloat162float(h));
}

// ---------------------------------------------------------------------------
// Elementwise split: fp32 [n] -> hi/lo bf16
// ---------------------------------------------------------------------------
__global__ __launch_bounds__(256) void conv_split_kernel(
    const float* __restrict__ in, __nv_bfloat16* __restrict__ hi,
    __nv_bfloat16* __restrict__ lo, int n)
{
    int i = (blockIdx.x * 256 + threadIdx.x) * 4;
    if (i >= n) return;
    float4 v = *(const float4*)(in + i);
    __nv_bfloat16 h[4], l[4];
    split_bf16(v.x, h[0], l[0]);
    split_bf16(v.y, h[1], l[1]);
    split_bf16(v.z, h[2], l[2]);
    split_bf16(v.w, h[3], l[3]);
    *(__nv_bfloat162*)(hi + i)     = __nv_bfloat162(h[0], h[1]);
    *(__nv_bfloat162*)(hi + i + 2) = __nv_bfloat162(h[2], h[3]);
    *(__nv_bfloat162*)(lo + i)     = __nv_bfloat162(l[0], l[1]);
    *(__nv_bfloat162*)(lo + i + 2) = __nv_bfloat162(l[2], l[3]);
}

// ---------------------------------------------------------------------------
// Transpose + split: W [K,N] fp32 -> Wt hi/lo bf16 [N,K]
// ---------------------------------------------------------------------------
__global__ __launch_bounds__(256) void conv_wt_kernel(
    const float* __restrict__ W, __nv_bfloat16* __restrict__ Thi,
    __nv_bfloat16* __restrict__ Tlo, int K, int N)
{
    __shared__ float t[32][33];
    const int bx = blockIdx.x * 32;   // N offset
    const int by = blockIdx.y * 32;   // K offset
    const int tx = threadIdx.x & 31;
    const int ty = threadIdx.x >> 5;  // 0..7
    #pragma unroll
    for (int i = 0; i < 4; ++i)
        t[ty + i * 8][tx] = W[(long)(by + ty + i * 8) * N + bx + tx];
    __syncthreads();
    #pragma unroll
    for (int i = 0; i < 4; ++i) {
        int n = bx + ty + i * 8;
        int k = by + tx;
        float v = t[tx][ty + i * 8];
        __nv_bfloat16 h, l;
        split_bf16(v, h, l);
        Thi[(long)n * K + k] = h;
        Tlo[(long)n * K + k] = l;
    }
}

// ---------------------------------------------------------------------------
// GEMM: split-bf16 3-MMA, ldmatrix, cp.async (R9 core).
// mode 0: plain C = A@B^T + bias (fp32).
// mode 1 (QKV): Q cols -> fp16*0.125 g_qh; K -> fp16 g_kh; V -> fp16 g_vh,
//               all laid out [b,h,s,d]; no fp32 C writes.
// ---------------------------------------------------------------------------
#define AHI_OFF 0
#define ALO_OFF 16384
#define BHI_OFF 32768
#define BLO_OFF 40960
#define STG_SZ  49152

__global__ __launch_bounds__(256, 2) void gemm_mma_kernel(
    const __nv_bfloat16* __restrict__ Ahi, const __nv_bfloat16* __restrict__ Alo,
    const __nv_bfloat16* __restrict__ Bhi, const __nv_bfloat16* __restrict__ Blo,
    const float* __restrict__ bias, float* __restrict__ C,
    int M, int N, int K, int mode)
{
    extern __shared__ char smem[];
    const uint32_t sbase = smem_u32(smem);

    const int tid  = threadIdx.x;
    const int lane = tid & 31;
    const int wid  = tid >> 5;
    const int wm   = (wid & 3) * 32;
    const int wn   = (wid >> 2) * 32;

    const long rowA = blockIdx.y * 128 + (tid >> 1);
    const int  ac0  = (tid & 1) * 4;
    const long rowB = blockIdx.x * 64 + (tid >> 2);
    const int  bc0  = (tid & 3) * 2;

    const __nv_bfloat16* pAh = Ahi + rowA * K + ac0 * 8;
    const __nv_bfloat16* pAl = Alo + rowA * K + ac0 * 8;
    const __nv_bfloat16* pBh = Bhi + rowB * K + bc0 * 8;
    const __nv_bfloat16* pBl = Blo + rowB * K + bc0 * 8;

    uint32_t aswz[4], bswz[2];
    #pragma unroll
    for (int j = 0; j < 4; ++j)
        aswz[j] = SWZ((tid >> 1) * 128 + (ac0 + j) * 16);
    #pragma unroll
    for (int j = 0; j < 2; ++j)
        bswz[j] = SWZ((tid >> 2) * 128 + (bc0 + j) * 16);

    auto load_chunk = [&](int ck, int s) {
        const uint32_t base = sbase + s * STG_SZ;
        const long go = (long)ck * 64;
        #pragma unroll
        for (int j = 0; j < 4; ++j) {
            cp_async16(base + AHI_OFF + aswz[j], pAh + go + j * 8);
            cp_async16(base + ALO_OFF + aswz[j], pAl + go + j * 8);
        }
        #pragma unroll
        for (int j = 0; j < 2; ++j) {
            cp_async16(base + BHI_OFF + bswz[j], pBh + go + j * 8);
            cp_async16(base + BLO_OFF + bswz[j], pBl + go + j * 8);
        }
    };

    const int a_row = (lane & 7) + ((lane >> 3) & 1) * 8;
    const int a_kc  = lane >> 4;
    const int b_row = (lane & 7) + ((lane >> 4) & 1) * 8;
    const int b_kc  = (lane >> 3) & 1;

    const int arow0 = (wm + a_row) * 128;
    const int arow1 = (wm + 16 + a_row) * 128;
    const int brow0 = (wn + b_row) * 128;
    const int brow1 = (wn + 16 + b_row) * 128;

    float acc[2][4][4];
    #pragma unroll
    for (int i = 0; i < 2; ++i)
        #pragma unroll
        for (int j = 0; j < 4; ++j)
            #pragma unroll
            for (int k = 0; k < 4; ++k) acc[i][j][k] = 0.0f;

    load_chunk(0, 0);
    CP_COMMIT();

    const int nk = K / 64;
    for (int t = 0; t < nk; ++t) {
        const int s = t & 1;
        const bool has_next = (t + 1 < nk);
        if (has_next) {
            load_chunk(t + 1, s ^ 1);
            CP_COMMIT();
            asm volatile("cp.async.wait_group 1;" ::: "memory");
        } else {
            asm volatile("cp.async.wait_group 0;" ::: "memory");
        }
        __syncthreads();

        const uint32_t sb = sbase + s * STG_SZ;
        #pragma unroll
        for (int ks = 0; ks < 4; ++ks) {
            const int akc = ks * 2 + a_kc;
            const int bkc = ks * 2 + b_kc;
            unsigned ah0[4], ah1[4], al0[4], al1[4];
            unsigned bh0[4], bh1[4], bl0[4], bl1[4];
            ldsm_x4(ah0[0], ah0[1], ah0[2], ah0[3], sb + AHI_OFF + SWZ(arow0 + akc * 16));
            ldsm_x4(ah1[0], ah1[1], ah1[2], ah1[3], sb + AHI_OFF + SWZ(arow1 + akc * 16));
            ldsm_x4(al0[0], al0[1], al0[2], al0[3], sb + ALO_OFF + SWZ(arow0 + akc * 16));
            ldsm_x4(al1[0], al1[1], al1[2], al1[3], sb + ALO_OFF + SWZ(arow1 + akc * 16));
            ldsm_x4(bh0[0], bh0[1], bh0[2], bh0[3], sb + BHI_OFF + SWZ(brow0 + bkc * 16));
            ldsm_x4(bh1[0], bh1[1], bh1[2], bh1[3], sb + BHI_OFF + SWZ(brow1 + bkc * 16));
            ldsm_x4(bl0[0], bl0[1], bl0[2], bl0[3], sb + BLO_OFF + SWZ(brow0 + bkc * 16));
            ldsm_x4(bl1[0], bl1[1], bl1[2], bl1[3], sb + BLO_OFF + SWZ(brow1 + bkc * 16));

            #pragma unroll
            for (int mf = 0; mf < 2; ++mf) {
                unsigned* ah = mf ? ah1 : ah0;
                unsigned* al = mf ? al1 : al0;
                #pragma unroll
                for (int nf2 = 0; nf2 < 2; ++nf2) {
                    unsigned* bh = nf2 ? bh1 : bh0;
                    unsigned* bl = nf2 ? bl1 : bl0;
                    #pragma unroll
                    for (int sub = 0; sub < 2; ++sub) {
                        float* c = acc[mf][nf2 * 2 + sub];
                        mma_bf16(c, ah[0], ah[1], ah[2], ah[3], bh[sub*2], bh[sub*2+1]);
                        mma_bf16(c, ah[0], ah[1], ah[2], ah[3], bl[sub*2], bl[sub*2+1]);
                        mma_bf16(c, al[0], al[1], al[2], al[3], bh[sub*2], bh[sub*2+1]);
                    }
                }
            }
        }
        __syncthreads();
    }

    // ---- epilogue ----
    const int gr = lane >> 2;
    const int gc = (lane & 3) * 2;
    const int region = (mode == 1) ? (int)(blockIdx.x >> 4) : 0;  // 0=Q,1=K,2=V
    __half* dsth = (region == 0) ? g_qh : (region == 1) ? g_kh : g_vh;
    const float osc = (mode == 1 && region == 0) ? 0.125f : 1.0f;

    #pragma unroll
    for (int mf = 0; mf < 2; ++mf) {
        #pragma unroll
        for (int nf = 0; nf < 4; ++nf) {
            int col = blockIdx.x * 64 + wn + nf * 8 + gc;
            float2 bi = *(const float2*)(bias + col);
            int row = blockIdx.y * 128 + wm + mf * 16 + gr;
            float v0 = acc[mf][nf][0] + bi.x, v1 = acc[mf][nf][1] + bi.y;
            float v2 = acc[mf][nf][2] + bi.x, v3 = acc[mf][nf][3] + bi.y;
            if (mode == 1) {
                int d  = col & 63;
                int hh = (col >> 6) & 15;
                int bb = row >> 11, s0 = row & 2047;
                long base = (((long)bb * Hq + hh) * Sq) * HDq + d;
                *(__half2*)&dsth[base + (long)s0 * HDq] =
                    __floats2half2_rn(v0 * osc, v1 * osc);
                *(__half2*)&dsth[base + (long)(s0 + 8) * HDq] =
                    __floats2half2_rn(v2 * osc, v3 * osc);
            } else {
                *(float2*)(C + (long)row * N + col)       = make_float2(v0, v1);
                *(float2*)(C + (long)(row + 8) * N + col) = make_float2(v2, v3);
            }
        }
    }
}

// ---------------------------------------------------------------------------
// Flash attention, all-fp16 operands: QK fp16 m16n8k16 (== tf32 precision),
// fp32 online softmax, fp16 PV. Q/K/V staged via cp.async (K/V double-buf).
// BM=128, 256 threads, grid (S/128, H, B).
// Dyn smem 48KB: Q->P 16KB | K 2x8KB | V 2x8KB. All [row][64 fp16] SWZ rows.
// ---------------------------------------------------------------------------
#define AQ_OFF 0
#define AK_OFF 16384
#define AV_OFF 32768
#define ATT_SMEM 49152
#define NKT (Sq / 64)

__global__ __launch_bounds__(256, 2) void attn_f16_kernel(
    const __half* __restrict__ qh, const __half* __restrict__ kh,
    const __half* __restrict__ vh,
    __nv_bfloat16* __restrict__ ohi, __nv_bfloat16* __restrict__ olo)
{
    extern __shared__ char asmem[];
    char* PB = asmem;                            // P fp16 (overlays Q)
    const uint32_t s_u = smem_u32(asmem);

    const int tid  = threadIdx.x;
    const int lane = tid & 31;
    const int wid  = tid >> 5;
    const int q    = lane >> 2;
    const int sq   = lane & 3;

    const int h    = blockIdx.y;
    const int b    = blockIdx.z;
    const int tok0 = b * Sq + blockIdx.x * 128;

    const char* qbase = (const char*)(qh +
        (((long)(b * Hq + h)) * Sq + blockIdx.x * 128) * HDq);
    const char* kbase = (const char*)(kh + ((long)(b * Hq + h)) * Sq * HDq);
    const char* vbase = (const char*)(vh + ((long)(b * Hq + h)) * Sq * HDq);

    // ---- prologue: Q (16KB) + K[0] + V[0] ----
    {
        uint32_t b0 = (uint32_t)tid * 64;
        #pragma unroll
        for (int j = 0; j < 4; ++j)
            cp_async16(s_u + AQ_OFF + SWZ(b0 + j * 16), qbase + b0 + j * 16);
        uint32_t c0 = (uint32_t)tid * 32;
        cp_async16(s_u + AK_OFF + SWZ(c0),      kbase + c0);
        cp_async16(s_u + AK_OFF + SWZ(c0 + 16), kbase + c0 + 16);
        cp_async16(s_u + AV_OFF + SWZ(c0),      vbase + c0);
        cp_async16(s_u + AV_OFF + SWZ(c0 + 16), vbase + c0 + 16);
        CP_COMMIT();
        asm volatile("cp.async.wait_group 0;" ::: "memory");
        __syncthreads();
    }

    const int rl   = wid * 16 + q;
    const int rl0  = wid * 16;
    const int l15  = lane & 15;
    const int l16  = (lane >> 4) & 1;
    const int bkr  = (lane & 7) + ((lane >> 4) & 1) * 8;   // non-trans B rows
    const int bkc  = (lane >> 3) & 1;

    // ---- Q fragments (own warp rows, m16k16 x 4 chunks) ----
    unsigned qf[4][4];
    #pragma unroll
    for (int kf = 0; kf < 4; ++kf)
        ldsm_x4(qf[kf][0], qf[kf][1], qf[kf][2], qf[kf][3],
                s_u + AQ_OFF + SWZ((rl0 + l15) * 128 + kf * 32 + l16 * 16));

    float O[8][4];
    #pragma unroll
    for (int nf = 0; nf < 8; ++nf)
        #pragma unroll
        for (int k = 0; k < 4; ++k) O[nf][k] = 0.0f;
    float m0 = -1e30f, m1 = -1e30f, l0 = 0.0f, l1 = 0.0f;

    for (int kt = 0; kt < NKT; ++kt) {
        const int st = kt & 1;
        __syncthreads();   // all warps done with stage st^1 and P region

        if (kt + 1 < NKT) {
            uint32_t c0 = (uint32_t)tid * 32;
            const char* ks = kbase + (long)(kt + 1) * 8192 + c0;
            const char* vs = vbase + (long)(kt + 1) * 8192 + c0;
            uint32_t kd = s_u + AK_OFF + (st ^ 1) * 8192;
            uint32_t vd = s_u + AV_OFF + (st ^ 1) * 8192;
            cp_async16(kd + SWZ(c0),      ks);
            cp_async16(kd + SWZ(c0 + 16), ks + 16);
            cp_async16(vd + SWZ(c0),      vs);
            cp_async16(vd + SWZ(c0 + 16), vs + 16);
            CP_COMMIT();
            asm volatile("cp.async.wait_group 1;" ::: "memory");
        } else {
            asm volatile("cp.async.wait_group 0;" ::: "memory");
        }
        __syncthreads();

        // ---- scores: sc = Q @ K^T (fp16 m16n8k16, ldmatrix frags) ----
        const uint32_t kst = s_u + AK_OFF + st * 8192;
        float sc[8][4];
        #pragma unroll
        for (int nf = 0; nf < 8; ++nf)
            sc[nf][0] = sc[nf][1] = sc[nf][2] = sc[nf][3] = 0.0f;
        #pragma unroll
        for (int kf = 0; kf < 4; ++kf) {
            #pragma unroll
            for (int cf = 0; cf < 4; ++cf) {
                unsigned kb0, kb1, kb2, kb3;
                ldsm_x4(kb0, kb1, kb2, kb3,
                        kst + SWZ((cf * 16 + bkr) * 128 + kf * 32 + bkc * 16));
                mma_f16(sc[cf * 2],     qf[kf][0], qf[kf][1], qf[kf][2], qf[kf][3], kb0, kb1);
                mma_f16(sc[cf * 2 + 1], qf[kf][0], qf[kf][1], qf[kf][2], qf[kf][3], kb2, kb3);
            }
        }

        // ---- online softmax ----
        float mx0 = -1e30f, mx1 = -1e30f;
        #pragma unroll
        for (int nf = 0; nf < 8; ++nf) {
            mx0 = fmaxf(mx0, fmaxf(sc[nf][0], sc[nf][1]));
            mx1 = fmaxf(mx1, fmaxf(sc[nf][2], sc[nf][3]));
        }
        mx0 = fmaxf(mx0, __shfl_xor_sync(0xffffffffu, mx0, 1));
        mx0 = fmaxf(mx0, __shfl_xor_sync(0xffffffffu, mx0, 2));
        mx1 = fmaxf(mx1, __shfl_xor_sync(0xffffffffu, mx1, 1));
        mx1 = fmaxf(mx1, __shfl_xor_sync(0xffffffffu, mx1, 2));
        float mn0 = fmaxf(m0, mx0), mn1 = fmaxf(m1, mx1);
        float al0 = __expf(m0 - mn0), al1 = __expf(m1 - mn1);
        float s0 = 0.0f, s1 = 0.0f;
        #pragma unroll
        for (int nf = 0; nf < 8; ++nf) {
            sc[nf][0] = __expf(sc[nf][0] - mn0);
            sc[nf][1] = __expf(sc[nf][1] - mn0);
            sc[nf][2] = __expf(sc[nf][2] - mn1);
            sc[nf][3] = __expf(sc[nf][3] - mn1);
            s0 += sc[nf][0] + sc[nf][1];
            s1 += sc[nf][2] + sc[nf][3];
        }
        s0 += __shfl_xor_sync(0xffffffffu, s0, 1);
        s0 += __shfl_xor_sync(0xffffffffu, s0, 2);
        s1 += __shfl_xor_sync(0xffffffffu, s1, 1);
        s1 += __shfl_xor_sync(0xffffffffu, s1, 2);
        l0 = l0 * al0 + s0;  m0 = mn0;
        l1 = l1 * al1 + s1;  m1 = mn1;
        #pragma unroll
        for (int nf = 0; nf < 8; ++nf) {
            O[nf][0] *= al0; O[nf][1] *= al0;
            O[nf][2] *= al1; O[nf][3] *= al1;
        }

        // ---- store P as fp16 (own warp rows; overlays Q region) ----
        #pragma unroll
        for (int nf = 0; nf < 8; ++nf) {
            unsigned pp0 = pack_f16x2(sc[nf][1], sc[nf][0]);
            unsigned pp1 = pack_f16x2(sc[nf][3], sc[nf][2]);
            *(unsigned*)(PB + SWZ(rl * 128 + nf * 16 + 4 * sq))       = pp0;
            *(unsigned*)(PB + SWZ((rl + 8) * 128 + nf * 16 + 4 * sq)) = pp1;
        }
        __syncwarp();

        // ---- O += P @ V  (fp16, trans ldmatrix on V [c][d]) ----
        const uint32_t vst = s_u + AV_OFF + st * 8192;
        #pragma unroll
        for (int kf = 0; kf < 4; ++kf) {
            unsigned pa0, pa1, pa2, pa3;
            ldsm_x4(pa0, pa1, pa2, pa3,
                    s_u + AQ_OFF + SWZ((rl0 + l15) * 128 + kf * 32 + l16 * 16));
            #pragma unroll
            for (int nfp = 0; nfp < 4; ++nfp) {
                unsigned vb0, vb1, vb2, vb3;
                ldsm_x4_t(vb0, vb1, vb2, vb3,
                          vst + SWZ((kf * 16 + l15) * 128 + nfp * 32 + l16 * 16));
                mma_f16(O[nfp * 2],     pa0, pa1, pa2, pa3, vb0, vb1);
                mma_f16(O[nfp * 2 + 1], pa0, pa1, pa2, pa3, vb2, vb3);
            }
        }
    }

    // ---- epilogue: normalize, write hi/lo bf16 split ----
    float inv0 = 1.0f / l0, inv1 = 1.0f / l1;
    #pragma unroll
    for (int nf = 0; nf < 8; ++nf) {
        int c = h * HDq + nf * 8 + 2 * sq;
        long i0 = (long)(tok0 + rl) * Dq + c;
        long i1 = (long)(tok0 + rl + 8) * Dq + c;
        __nv_bfloat16 h0, l0b, h1, l1b;
        split_bf16(O[nf][0] * inv0, h0, l0b);
        split_bf16(O[nf][1] * inv0, h1, l1b);
        *(__nv_bfloat162*)(ohi + i0) = __nv_bfloat162(h0, h1);
        *(__nv_bfloat162*)(olo + i0) = __nv_bfloat162(l0b, l1b);
        split_bf16(O[nf][2] * inv1, h0, l0b);
        split_bf16(O[nf][3] * inv1, h1, l1b);
        *(__nv_bfloat162*)(ohi + i1) = __nv_bfloat162(h0, h1);
        *(__nv_bfloat162*)(olo + i1) = __nv_bfloat162(l0b, l1b);
    }
}

// ---------------------------------------------------------------------------
// Launch
// ---------------------------------------------------------------------------
extern "C" void kernel_launch(void* const* d_in, const int* in_sizes, int n_in,
                              void* d_out, int out_size)
{
    const float* x      = (const float*)d_in[0];
    const float* W_qkv  = (const float*)d_in[1];
    const float* b_qkv  = (const float*)d_in[2];
    const float* W_proj = (const float*)d_in[3];
    const float* b_proj = (const float*)d_in[4];
    float* outp = (float*)d_out;

    __half *qhp, *khp, *vhp;
    __nv_bfloat16 *xhi, *xlo, *wqh, *wql, *wph, *wpl, *ahi, *alo;
    cudaGetSymbolAddress((void**)&qhp, g_qh);
    cudaGetSymbolAddress((void**)&khp, g_kh);
    cudaGetSymbolAddress((void**)&vhp, g_vh);
    cudaGetSymbolAddress((void**)&xhi, g_xhi);
    cudaGetSymbolAddress((void**)&xlo, g_xlo);
    cudaGetSymbolAddress((void**)&wqh, g_wqkvt_hi);
    cudaGetSymbolAddress((void**)&wql, g_wqkvt_lo);
    cudaGetSymbolAddress((void**)&wph, g_wprot_hi);
    cudaGetSymbolAddress((void**)&wpl, g_wprot_lo);
    cudaGetSymbolAddress((void**)&ahi, g_ahi);
    cudaGetSymbolAddress((void**)&alo, g_alo);

    cudaFuncSetAttribute(gemm_mma_kernel,
                         cudaFuncAttributeMaxDynamicSharedMemorySize, 2 * STG_SZ);
    cudaFuncSetAttribute(attn_f16_kernel,
                         cudaFuncAttributeMaxDynamicSharedMemorySize, ATT_SMEM);

    // 0) precision splits
    conv_split_kernel<<<(NTOK * Dq) / 1024, 256>>>(x, xhi, xlo, NTOK * Dq);
    {
        dim3 grid(QKVN / 32, Dq / 32);
        conv_wt_kernel<<<grid, 256>>>(W_qkv, wqh, wql, Dq, QKVN);
    }
    {
        dim3 grid(Dq / 32, Dq / 32);
        conv_wt_kernel<<<grid, 256>>>(W_proj, wph, wpl, Dq, Dq);
    }

    // 1) QKV projection (mode 1: writes Q/K/V fp16 [b,h,s,d])
    {
        dim3 grid(QKVN / 64, NTOK / 128);
        gemm_mma_kernel<<<grid, 256, 2 * STG_SZ>>>(xhi, xlo, wqh, wql, b_qkv,
                                                   (float*)0, NTOK, QKVN, Dq, 1);
    }
    // 2) Attention (all fp16 tensor ops), writes hi/lo split
    {
        dim3 grid(Sq / 128, Hq, Bq);
        attn_f16_kernel<<<grid, 256, ATT_SMEM>>>(qhp, khp, vhp, ahi, alo);
    }
    // 3) Output projection (mode 0)
    {
        dim3 grid(Dq / 64, NTOK / 128);
        gemm_mma_kernel<<<grid, 256, 2 * STG_SZ>>>(ahi, alo, wph, wpl, b_proj, outp,
                                                   NTOK, Dq, Dq, 0);
    }
}

// round 17
// speedup vs baseline: 5.9296x; 1.6393x over previous
#include <cuda_runtime.h>
#include <cuda_bf16.h>
#include <cuda_fp16.h>
#include <cstdint>

// Problem constants
#define Bq   2
#define Sq   2048
#define Dq   1024
#define Hq   16
#define HDq  64
#define NTOK (Bq * Sq)          // 4096
#define QKVN (3 * Dq)           // 3072

// Scratch (device globals: allocation-free rule)
__device__ __half g_qh[NTOK * Dq];                   // Q fp16 [b,h,s,d], pre-scaled
__device__ __half g_kh[NTOK * Dq];                   // K fp16 [b,h,s,d]
__device__ __half g_vh[NTOK * Dq];                   // V fp16 [b,h,s,d]
__device__ __half g_xh[NTOK * Dq];                   // x fp16 [tok][D]
__device__ __half g_wqt[QKVN * Dq];                  // W_qkv^T fp16 [N,K]
__device__ __half g_wpt[Dq * Dq];                    // W_proj^T fp16 [N,K]
__device__ __half g_ah[NTOK * Dq];                   // attention out fp16 [tok][D]

// ---------------------------------------------------------------------------
// Helpers
// ---------------------------------------------------------------------------
__device__ __forceinline__ uint32_t smem_u32(const void* p)
{
    uint32_t a;
    asm("{ .reg .u64 t; cvta.to.shared.u64 t, %1; cvt.u32.u64 %0, t; }"
        : "=r"(a) : "l"(p));
    return a;
}

#define SWZ(x) ((x) ^ (((x) >> 3) & 0x70))

__device__ __forceinline__ void cp_async16(uint32_t dst, const void* src)
{
    asm volatile("cp.async.cg.shared.global [%0], [%1], 16;" :: "r"(dst), "l"(src));
}
#define CP_COMMIT() asm volatile("cp.async.commit_group;" ::: "memory")

__device__ __forceinline__ void ldsm_x4(unsigned& r0, unsigned& r1,
                                        unsigned& r2, unsigned& r3, uint32_t a)
{
    asm volatile("ldmatrix.sync.aligned.m8n8.x4.shared.b16 {%0,%1,%2,%3}, [%4];"
                 : "=r"(r0), "=r"(r1), "=r"(r2), "=r"(r3) : "r"(a));
}

__device__ __forceinline__ void ldsm_x4_t(unsigned& r0, unsigned& r1,
                                          unsigned& r2, unsigned& r3, uint32_t a)
{
    asm volatile("ldmatrix.sync.aligned.m8n8.x4.trans.shared.b16 {%0,%1,%2,%3}, [%4];"
                 : "=r"(r0), "=r"(r1), "=r"(r2), "=r"(r3) : "r"(a));
}

__device__ __forceinline__ void mma_f16(float* c, unsigned a0, unsigned a1,
                                        unsigned a2, unsigned a3,
                                        unsigned b0, unsigned b1)
{
    asm volatile(
        "mma.sync.aligned.m16n8k16.row.col.f32.f16.f16.f32 "
        "{%0,%1,%2,%3}, {%4,%5,%6,%7}, {%8,%9}, {%0,%1,%2,%3};\n"
        : "+f"(c[0]), "+f"(c[1]), "+f"(c[2]), "+f"(c[3])
        : "r"(a0), "r"(a1), "r"(a2), "r"(a3), "r"(b0), "r"(b1));
}

__device__ __forceinline__ unsigned pack_f16x2(float hi, float lo)
{
    unsigned d;
    asm("cvt.rn.f16x2.f32 %0, %1, %2;" : "=r"(d) : "f"(hi), "f"(lo));
    return d;
}

// ---------------------------------------------------------------------------
// Elementwise fp32 -> fp16
// ---------------------------------------------------------------------------
__global__ __launch_bounds__(256) void conv_h_kernel(
    const float* __restrict__ in, __half* __restrict__ out, int n)
{
    int i = (blockIdx.x * 256 + threadIdx.x) * 4;
    if (i >= n) return;
    float4 v = *(const float4*)(in + i);
    *(unsigned*)(out + i)     = pack_f16x2(v.y, v.x);
    *(unsigned*)(out + i + 2) = pack_f16x2(v.w, v.z);
}

// ---------------------------------------------------------------------------
// Transpose: W [K,N] fp32 -> Wt fp16 [N,K]
// ---------------------------------------------------------------------------
__global__ __launch_bounds__(256) void conv_wt_kernel(
    const float* __restrict__ W, __half* __restrict__ T, int K, int N)
{
    __shared__ float t[32][33];
    const int bx = blockIdx.x * 32;   // N offset
    const int by = blockIdx.y * 32;   // K offset
    const int tx = threadIdx.x & 31;
    const int ty = threadIdx.x >> 5;  // 0..7
    #pragma unroll
    for (int i = 0; i < 4; ++i)
        t[ty + i * 8][tx] = W[(long)(by + ty + i * 8) * N + bx + tx];
    __syncthreads();
    #pragma unroll
    for (int i = 0; i < 4; ++i) {
        int n = bx + ty + i * 8;
        int k = by + tx;
        T[(long)n * K + k] = __float2half_rn(t[tx][ty + i * 8]);
    }
}

// ---------------------------------------------------------------------------
// GEMM fp16: C[M,N] = A[M,K] @ Bt[N,K]^T + bias.  Single-MMA (fp16 in,
// fp32 acc). Tile 128x128, BK=64, cp.async double buffer, ldmatrix.
// 256 threads = 8 warps, warp grid 4(m) x 2(n), warp tile 32x64.
// Dyn smem: 2 stages x (A 16KB + B 16KB) = 64KB.
// mode 0: fp32 C. mode 1 (QKV): Q*0.125/K/V -> fp16 [b,h,s,d] buffers.
// ---------------------------------------------------------------------------
#define GA_OFF 0
#define GB_OFF 16384
#define GSTG   32768

__global__ __launch_bounds__(256, 2) void gemm_f16_kernel(
    const __half* __restrict__ Ah, const __half* __restrict__ Bh,
    const float* __restrict__ bias, float* __restrict__ C,
    int M, int N, int K, int mode)
{
    extern __shared__ char smem[];
    const uint32_t sbase = smem_u32(smem);

    const int tid  = threadIdx.x;
    const int lane = tid & 31;
    const int wid  = tid >> 5;
    const int wm   = (wid & 3) * 32;
    const int wn   = (wid >> 2) * 64;

    // ---- global load mapping (A and B symmetric: 128 rows x 128B) ----
    const long rowA = blockIdx.y * 128 + (tid >> 1);
    const long rowB = blockIdx.x * 128 + (tid >> 1);
    const int  c0   = (tid & 1) * 4;          // 16B-unit base within row
    const __half* pA = Ah + rowA * K + c0 * 8;
    const __half* pB = Bh + rowB * K + c0 * 8;
    uint32_t swz[4];
    #pragma unroll
    for (int j = 0; j < 4; ++j)
        swz[j] = SWZ((tid >> 1) * 128 + (c0 + j) * 16);

    auto load_chunk = [&](int ck, int s) {
        const uint32_t base = sbase + s * GSTG;
        const long go = (long)ck * 64;
        #pragma unroll
        for (int j = 0; j < 4; ++j) {
            cp_async16(base + GA_OFF + swz[j], pA + go + j * 8);
            cp_async16(base + GB_OFF + swz[j], pB + go + j * 8);
        }
    };

    // ---- ldmatrix lane mapping ----
    const int a_row = (lane & 7) + ((lane >> 3) & 1) * 8;
    const int a_kc  = lane >> 4;
    const int b_row = (lane & 7) + ((lane >> 4) & 1) * 8;
    const int b_kc  = (lane >> 3) & 1;

    const int arow0 = (wm + a_row) * 128;
    const int arow1 = (wm + 16 + a_row) * 128;
    int brow[4];
    #pragma unroll
    for (int j = 0; j < 4; ++j)
        brow[j] = (wn + j * 16 + b_row) * 128;

    float acc[2][8][4];
    #pragma unroll
    for (int i = 0; i < 2; ++i)
        #pragma unroll
        for (int j = 0; j < 8; ++j)
            #pragma unroll
            for (int k = 0; k < 4; ++k) acc[i][j][k] = 0.0f;

    load_chunk(0, 0);
    CP_COMMIT();

    const int nk = K / 64;
    for (int t = 0; t < nk; ++t) {
        const int s = t & 1;
        const bool has_next = (t + 1 < nk);
        if (has_next) {
            load_chunk(t + 1, s ^ 1);
            CP_COMMIT();
            asm volatile("cp.async.wait_group 1;" ::: "memory");
        } else {
            asm volatile("cp.async.wait_group 0;" ::: "memory");
        }
        __syncthreads();

        const uint32_t sb = sbase + s * GSTG;
        #pragma unroll
        for (int ks = 0; ks < 4; ++ks) {
            const int akc = ks * 2 + a_kc;
            const int bkc = ks * 2 + b_kc;
            unsigned a0[4], a1[4], bf[4][4];
            ldsm_x4(a0[0], a0[1], a0[2], a0[3], sb + GA_OFF + SWZ(arow0 + akc * 16));
            ldsm_x4(a1[0], a1[1], a1[2], a1[3], sb + GA_OFF + SWZ(arow1 + akc * 16));
            #pragma unroll
            for (int j = 0; j < 4; ++j)
                ldsm_x4(bf[j][0], bf[j][1], bf[j][2], bf[j][3],
                        sb + GB_OFF + SWZ(brow[j] + bkc * 16));

            #pragma unroll
            for (int mf = 0; mf < 2; ++mf) {
                unsigned* aa = mf ? a1 : a0;
                #pragma unroll
                for (int j = 0; j < 4; ++j) {
                    #pragma unroll
                    for (int sub = 0; sub < 2; ++sub)
                        mma_f16(acc[mf][j * 2 + sub], aa[0], aa[1], aa[2], aa[3],
                                bf[j][sub * 2], bf[j][sub * 2 + 1]);
                }
            }
        }
        __syncthreads();
    }

    // ---- epilogue ----
    const int gr = lane >> 2;
    const int gc = (lane & 3) * 2;
    const int region = (mode == 1) ? (int)(blockIdx.x >> 3) : 0;  // 0=Q,1=K,2=V
    __half* dsth = (region == 0) ? g_qh : (region == 1) ? g_kh : g_vh;
    const float osc = (mode == 1 && region == 0) ? 0.125f : 1.0f;

    #pragma unroll
    for (int mf = 0; mf < 2; ++mf) {
        #pragma unroll
        for (int nf = 0; nf < 8; ++nf) {
            int col = blockIdx.x * 128 + wn + nf * 8 + gc;
            float2 bi = *(const float2*)(bias + col);
            int row = blockIdx.y * 128 + wm + mf * 16 + gr;
            float v0 = acc[mf][nf][0] + bi.x, v1 = acc[mf][nf][1] + bi.y;
            float v2 = acc[mf][nf][2] + bi.x, v3 = acc[mf][nf][3] + bi.y;
            if (mode == 1) {
                int d  = col & 63;
                int hh = (col >> 6) & 15;
                int bb = row >> 11, s0 = row & 2047;
                long base = (((long)bb * Hq + hh) * Sq) * HDq + d;
                *(unsigned*)&dsth[base + (long)s0 * HDq] =
                    pack_f16x2(v1 * osc, v0 * osc);
                *(unsigned*)&dsth[base + (long)(s0 + 8) * HDq] =
                    pack_f16x2(v3 * osc, v2 * osc);
            } else {
                *(float2*)(C + (long)row * N + col)       = make_float2(v0, v1);
                *(float2*)(C + (long)(row + 8) * N + col) = make_float2(v2, v3);
            }
        }
    }
}

// ---------------------------------------------------------------------------
// Flash attention, all-fp16 operands (R16 core). Output fp16 single.
// BM=128, 256 threads, grid (S/128, H, B).
// Dyn smem 48KB: Q->P 16KB | K 2x8KB | V 2x8KB.
// ---------------------------------------------------------------------------
#define AQ_OFF 0
#define AK_OFF 16384
#define AV_OFF 32768
#define ATT_SMEM 49152
#define NKT (Sq / 64)

__global__ __launch_bounds__(256, 2) void attn_f16_kernel(
    const __half* __restrict__ qh, const __half* __restrict__ kh,
    const __half* __restrict__ vh, __half* __restrict__ oh)
{
    extern __shared__ char asmem[];
    char* PB = asmem;                            // P fp16 (overlays Q)
    const uint32_t s_u = smem_u32(asmem);

    const int tid  = threadIdx.x;
    const int lane = tid & 31;
    const int wid  = tid >> 5;
    const int q    = lane >> 2;
    const int sq   = lane & 3;

    const int h    = blockIdx.y;
    const int b    = blockIdx.z;
    const int tok0 = b * Sq + blockIdx.x * 128;

    const char* qbase = (const char*)(qh +
        (((long)(b * Hq + h)) * Sq + blockIdx.x * 128) * HDq);
    const char* kbase = (const char*)(kh + ((long)(b * Hq + h)) * Sq * HDq);
    const char* vbase = (const char*)(vh + ((long)(b * Hq + h)) * Sq * HDq);

    // ---- prologue: Q (16KB) + K[0] + V[0] ----
    {
        uint32_t b0 = (uint32_t)tid * 64;
        #pragma unroll
        for (int j = 0; j < 4; ++j)
            cp_async16(s_u + AQ_OFF + SWZ(b0 + j * 16), qbase + b0 + j * 16);
        uint32_t c0 = (uint32_t)tid * 32;
        cp_async16(s_u + AK_OFF + SWZ(c0),      kbase + c0);
        cp_async16(s_u + AK_OFF + SWZ(c0 + 16), kbase + c0 + 16);
        cp_async16(s_u + AV_OFF + SWZ(c0),      vbase + c0);
        cp_async16(s_u + AV_OFF + SWZ(c0 + 16), vbase + c0 + 16);
        CP_COMMIT();
        asm volatile("cp.async.wait_group 0;" ::: "memory");
        __syncthreads();
    }

    const int rl   = wid * 16 + q;
    const int rl0  = wid * 16;
    const int l15  = lane & 15;
    const int l16  = (lane >> 4) & 1;
    const int bkr  = (lane & 7) + ((lane >> 4) & 1) * 8;
    const int bkc  = (lane >> 3) & 1;

    // ---- Q fragments (own warp rows) ----
    unsigned qf[4][4];
    #pragma unroll
    for (int kf = 0; kf < 4; ++kf)
        ldsm_x4(qf[kf][0], qf[kf][1], qf[kf][2], qf[kf][3],
                s_u + AQ_OFF + SWZ((rl0 + l15) * 128 + kf * 32 + l16 * 16));

    float O[8][4];
    #pragma unroll
    for (int nf = 0; nf < 8; ++nf)
        #pragma unroll
        for (int k = 0; k < 4; ++k) O[nf][k] = 0.0f;
    float m0 = -1e30f, m1 = -1e30f, l0 = 0.0f, l1 = 0.0f;

    for (int kt = 0; kt < NKT; ++kt) {
        const int st = kt & 1;
        __syncthreads();

        if (kt + 1 < NKT) {
            uint32_t c0 = (uint32_t)tid * 32;
            const char* ks = kbase + (long)(kt + 1) * 8192 + c0;
            const char* vs = vbase + (long)(kt + 1) * 8192 + c0;
            uint32_t kd = s_u + AK_OFF + (st ^ 1) * 8192;
            uint32_t vd = s_u + AV_OFF + (st ^ 1) * 8192;
            cp_async16(kd + SWZ(c0),      ks);
            cp_async16(kd + SWZ(c0 + 16), ks + 16);
            cp_async16(vd + SWZ(c0),      vs);
            cp_async16(vd + SWZ(c0 + 16), vs + 16);
            CP_COMMIT();
            asm volatile("cp.async.wait_group 1;" ::: "memory");
        } else {
            asm volatile("cp.async.wait_group 0;" ::: "memory");
        }
        __syncthreads();

        // ---- scores: sc = Q @ K^T ----
        const uint32_t kst = s_u + AK_OFF + st * 8192;
        float sc[8][4];
        #pragma unroll
        for (int nf = 0; nf < 8; ++nf)
            sc[nf][0] = sc[nf][1] = sc[nf][2] = sc[nf][3] = 0.0f;
        #pragma unroll
        for (int kf = 0; kf < 4; ++kf) {
            #pragma unroll
            for (int cf = 0; cf < 4; ++cf) {
                unsigned kb0, kb1, kb2, kb3;
                ldsm_x4(kb0, kb1, kb2, kb3,
                        kst + SWZ((cf * 16 + bkr) * 128 + kf * 32 + bkc * 16));
                mma_f16(sc[cf * 2],     qf[kf][0], qf[kf][1], qf[kf][2], qf[kf][3], kb0, kb1);
                mma_f16(sc[cf * 2 + 1], qf[kf][0], qf[kf][1], qf[kf][2], qf[kf][3], kb2, kb3);
            }
        }

        // ---- online softmax ----
        float mx0 = -1e30f, mx1 = -1e30f;
        #pragma unroll
        for (int nf = 0; nf < 8; ++nf) {
            mx0 = fmaxf(mx0, fmaxf(sc[nf][0], sc[nf][1]));
            mx1 = fmaxf(mx1, fmaxf(sc[nf][2], sc[nf][3]));
        }
        mx0 = fmaxf(mx0, __shfl_xor_sync(0xffffffffu, mx0, 1));
        mx0 = fmaxf(mx0, __shfl_xor_sync(0xffffffffu, mx0, 2));
        mx1 = fmaxf(mx1, __shfl_xor_sync(0xffffffffu, mx1, 1));
        mx1 = fmaxf(mx1, __shfl_xor_sync(0xffffffffu, mx1, 2));
        float mn0 = fmaxf(m0, mx0), mn1 = fmaxf(m1, mx1);
        float al0 = __expf(m0 - mn0), al1 = __expf(m1 - mn1);
        float s0 = 0.0f, s1 = 0.0f;
        #pragma unroll
        for (int nf = 0; nf < 8; ++nf) {
            sc[nf][0] = __expf(sc[nf][0] - mn0);
            sc[nf][1] = __expf(sc[nf][1] - mn0);
            sc[nf][2] = __expf(sc[nf][2] - mn1);
            sc[nf][3] = __expf(sc[nf][3] - mn1);
            s0 += sc[nf][0] + sc[nf][1];
            s1 += sc[nf][2] + sc[nf][3];
        }
        s0 += __shfl_xor_sync(0xffffffffu, s0, 1);
        s0 += __shfl_xor_sync(0xffffffffu, s0, 2);
        s1 += __shfl_xor_sync(0xffffffffu, s1, 1);
        s1 += __shfl_xor_sync(0xffffffffu, s1, 2);
        l0 = l0 * al0 + s0;  m0 = mn0;
        l1 = l1 * al1 + s1;  m1 = mn1;
        #pragma unroll
        for (int nf = 0; nf < 8; ++nf) {
            O[nf][0] *= al0; O[nf][1] *= al0;
            O[nf][2] *= al1; O[nf][3] *= al1;
        }

        // ---- store P as fp16 (own warp rows; overlays Q region) ----
        #pragma unroll
        for (int nf = 0; nf < 8; ++nf) {
            unsigned pp0 = pack_f16x2(sc[nf][1], sc[nf][0]);
            unsigned pp1 = pack_f16x2(sc[nf][3], sc[nf][2]);
            *(unsigned*)(PB + SWZ(rl * 128 + nf * 16 + 4 * sq))       = pp0;
            *(unsigned*)(PB + SWZ((rl + 8) * 128 + nf * 16 + 4 * sq)) = pp1;
        }
        __syncwarp();

        // ---- O += P @ V ----
        const uint32_t vst = s_u + AV_OFF + st * 8192;
        #pragma unroll
        for (int kf = 0; kf < 4; ++kf) {
            unsigned pa0, pa1, pa2, pa3;
            ldsm_x4(pa0, pa1, pa2, pa3,
                    s_u + AQ_OFF + SWZ((rl0 + l15) * 128 + kf * 32 + l16 * 16));
            #pragma unroll
            for (int nfp = 0; nfp < 4; ++nfp) {
                unsigned vb0, vb1, vb2, vb3;
                ldsm_x4_t(vb0, vb1, vb2, vb3,
                          vst + SWZ((kf * 16 + l15) * 128 + nfp * 32 + l16 * 16));
                mma_f16(O[nfp * 2],     pa0, pa1, pa2, pa3, vb0, vb1);
                mma_f16(O[nfp * 2 + 1], pa0, pa1, pa2, pa3, vb2, vb3);
            }
        }
    }

    // ---- epilogue: normalize, write fp16 [tok][D] ----
    float inv0 = 1.0f / l0, inv1 = 1.0f / l1;
    #pragma unroll
    for (int nf = 0; nf < 8; ++nf) {
        int c = h * HDq + nf * 8 + 2 * sq;
        long i0 = (long)(tok0 + rl) * Dq + c;
        long i1 = (long)(tok0 + rl + 8) * Dq + c;
        *(unsigned*)(oh + i0) = pack_f16x2(O[nf][1] * inv0, O[nf][0] * inv0);
        *(unsigned*)(oh + i1) = pack_f16x2(O[nf][3] * inv1, O[nf][2] * inv1);
    }
}

// ---------------------------------------------------------------------------
// Launch
// ---------------------------------------------------------------------------
extern "C" void kernel_launch(void* const* d_in, const int* in_sizes, int n_in,
                              void* d_out, int out_size)
{
    const float* x      = (const float*)d_in[0];
    const float* W_qkv  = (const float*)d_in[1];
    const float* b_qkv  = (const float*)d_in[2];
    const float* W_proj = (const float*)d_in[3];
    const float* b_proj = (const float*)d_in[4];
    float* outp = (float*)d_out;

    __half *qhp, *khp, *vhp, *xhp, *wqtp, *wptp, *ahp;
    cudaGetSymbolAddress((void**)&qhp, g_qh);
    cudaGetSymbolAddress((void**)&khp, g_kh);
    cudaGetSymbolAddress((void**)&vhp, g_vh);
    cudaGetSymbolAddress((void**)&xhp, g_xh);
    cudaGetSymbolAddress((void**)&wqtp, g_wqt);
    cudaGetSymbolAddress((void**)&wptp, g_wpt);
    cudaGetSymbolAddress((void**)&ahp, g_ah);

    cudaFuncSetAttribute(gemm_f16_kernel,
                         cudaFuncAttributeMaxDynamicSharedMemorySize, 2 * GSTG);
    cudaFuncSetAttribute(attn_f16_kernel,
                         cudaFuncAttributeMaxDynamicSharedMemorySize, ATT_SMEM);

    // 0) fp16 conversions
    conv_h_kernel<<<(NTOK * Dq) / 1024, 256>>>(x, xhp, NTOK * Dq);
    {
        dim3 grid(QKVN / 32, Dq / 32);
        conv_wt_kernel<<<grid, 256>>>(W_qkv, wqtp, Dq, QKVN);
    }
    {
        dim3 grid(Dq / 32, Dq / 32);
        conv_wt_kernel<<<grid, 256>>>(W_proj, wptp, Dq, Dq);
    }

    // 1) QKV projection (mode 1: writes Q/K/V fp16 [b,h,s,d])
    {
        dim3 grid(QKVN / 128, NTOK / 128);
        gemm_f16_kernel<<<grid, 256, 2 * GSTG>>>(xhp, wqtp, b_qkv,
                                                 (float*)0, NTOK, QKVN, Dq, 1);
    }
    // 2) Attention (all fp16 tensor ops), writes fp16 [tok][D]
    {
        dim3 grid(Sq / 128, Hq, Bq);
        attn_f16_kernel<<<grid, 256, ATT_SMEM>>>(qhp, khp, vhp, ahp);
    }
    // 3) Output projection (mode 0: fp32 out + bias)
    {
        dim3 grid(Dq / 128, NTOK / 128);
        gemm_f16_kernel<<<grid, 256, 2 * GSTG>>>(ahp, wptp, b_proj, outp,
                                                 NTOK, Dq, Dq, 0);
    }
}